// round 8
// baseline (speedup 1.0000x reference)
#include <cuda_runtime.h>
#include <cuda_bf16.h>

#define T 1024
#define D 1024
#define H 16
#define DHD 64
#define DFF 4096

// ---------------- static scratch (device globals; no allocation) ----------------
__device__ float g_hs[T * D];
__device__ float g_hbuf[T * D];
__device__ float g_q[T * D];
__device__ float g_k[T * D];
__device__ float g_v[T * D];
__device__ float g_beta[T * H];
__device__ float g_qk[T * H];
__device__ float g_o[T * D];
__device__ float g_kc[T * D];
__device__ float g_vc[T * D];
__device__ float g_kcr[T * D];
__device__ float g_scores[(size_t)H * T * T];
__device__ float g_ff1[T * DFF];
__device__ float g_ff2[T * DFF];
__device__ float g_cos[T * 32];
__device__ float g_sin[T * 32];

// ---------------- embedding gather ----------------
__global__ void embed_k(const int* __restrict__ ids, const float* __restrict__ emb,
                        float* __restrict__ out) {
    int t = blockIdx.x;
    int id = ids[t];
    for (int i = threadIdx.x; i < D; i += 256)
        out[(size_t)t * D + i] = emb[(size_t)id * D + i];
}

// ---------------- rope tables ----------------
__global__ void rope_tab_k(float* __restrict__ ct, float* __restrict__ st) {
    int t = blockIdx.x, i = threadIdx.x;  // i in [0,32)
    float inv = __powf(10000.0f, -(float)i / 32.0f);
    float f = (float)t * inv;
    ct[t * 32 + i] = cosf(f);
    st[t * 32 + i] = sinf(f);
}

// rope apply on [T, H, 64]; in may equal out
__global__ void rope_apply_k(const float* __restrict__ in, float* __restrict__ out,
                             const float* __restrict__ ct, const float* __restrict__ st) {
    int idx = blockIdx.x * 256 + threadIdx.x;  // T*H*32 total
    if (idx >= T * H * 32) return;
    int d = idx & 31;
    int th = idx >> 5;
    int h = th & (H - 1);
    int t = th >> 4;
    float c = ct[t * 32 + d], s = st[t * 32 + d];
    const float* pi = in + (size_t)t * D + h * DHD;
    float* po = out + (size_t)t * D + h * DHD;
    float x0 = pi[d], x1 = pi[d + 32];
    po[d] = x0 * c - x1 * s;
    po[d + 32] = x1 * c + x0 * s;
}

// ---------------- tf32 helpers ----------------
__device__ __forceinline__ unsigned f2tf(float x) {
    unsigned r;
    asm("cvt.rna.tf32.f32 %0, %1;" : "=r"(r) : "f"(x));
    return r;
}
__device__ __forceinline__ void tf_split(float x, unsigned& hi, unsigned& lo) {
    hi = f2tf(x);
    lo = f2tf(x - __uint_as_float(hi));
}
__device__ __forceinline__ void mma_tf32(float* d, unsigned a0, unsigned a1, unsigned a2,
                                         unsigned a3, unsigned b0, unsigned b1) {
    asm volatile(
        "mma.sync.aligned.m16n8k8.row.col.f32.tf32.tf32.f32 "
        "{%0,%1,%2,%3}, {%4,%5,%6,%7}, {%8,%9}, {%0,%1,%2,%3};"
        : "+f"(d[0]), "+f"(d[1]), "+f"(d[2]), "+f"(d[3])
        : "r"(a0), "r"(a1), "r"(a2), "r"(a3), "r"(b0), "r"(b1));
}

// ---------------- tensor-core GEMM (3xTF32, fp32-accurate) — R3 exact config ----------------
// C = act(A@B + bias) [*mul] [+res].  Requires M%64==0, N%64==0, K%16==0.
// 64x64x16 tile, 256 threads = 8 warps in 2x4 grid, warp tile 32x16.
__global__ __launch_bounds__(256) void tcgemm_k(
        const float* __restrict__ A, const float* __restrict__ Bm,
        const float* __restrict__ bias, const float* __restrict__ mulb,
        const float* __restrict__ resb, float* __restrict__ C,
        int M, int N, int K, int lda, int ldb, int ldc,
        long sA, long sB, long sC, int act) {
    int bz = blockIdx.z;
    A += (long)bz * sA;
    Bm += (long)bz * sB;
    C += (long)bz * sC;
    const float* mulp = mulb ? mulb + (long)bz * sC : nullptr;
    const float* resp = resb ? resb + (long)bz * sC : nullptr;

    int bm = blockIdx.y * 64, bn = blockIdx.x * 64;

    __shared__ float As[64][17];  // [m][k], padded
    __shared__ float Bs[16][68];  // [k][n], padded

    int tid = threadIdx.x;
    int lane = tid & 31;
    int warp = tid >> 5;
    int wm = warp >> 2;   // 0..1 -> rows wm*32
    int wn = warp & 3;    // 0..3 -> cols wn*16
    int grp = lane >> 2;  // 0..7
    int tig = lane & 3;   // 0..3

    // global staging maps
    int arow = tid >> 2;            // 0..63
    int acol = (tid & 3) * 4;       // 0,4,8,12
    int brow = tid >> 4;            // 0..15
    int bcol = (tid & 15) * 4;      // 0..60

    float4 aR, bR;
    auto gload = [&](int k0) {
        aR = *(const float4*)(A + (long)(bm + arow) * lda + k0 + acol);
        bR = *(const float4*)(Bm + (long)(k0 + brow) * ldb + bn + bcol);
    };
    auto sstore = [&]() {
        As[arow][acol + 0] = aR.x;
        As[arow][acol + 1] = aR.y;
        As[arow][acol + 2] = aR.z;
        As[arow][acol + 3] = aR.w;
        Bs[brow][bcol + 0] = bR.x;
        Bs[brow][bcol + 1] = bR.y;
        Bs[brow][bcol + 2] = bR.z;
        Bs[brow][bcol + 3] = bR.w;
    };

    float acc[2][2][4];
#pragma unroll
    for (int i = 0; i < 2; i++)
#pragma unroll
        for (int j = 0; j < 2; j++)
#pragma unroll
            for (int r = 0; r < 4; r++) acc[i][j][r] = 0.f;

    gload(0);
    sstore();
    __syncthreads();

    for (int k0 = 0; k0 < K; k0 += 16) {
        bool more = (k0 + 16) < K;
        if (more) gload(k0 + 16);

#pragma unroll
        for (int ks = 0; ks < 2; ks++) {
            int kk = ks * 8 + tig;
            // A fragments (2 m-tiles), split hi/lo
            unsigned ah[2][4], al[2][4];
#pragma unroll
            for (int mt = 0; mt < 2; mt++) {
                int m = wm * 32 + mt * 16 + grp;
                float a0 = As[m][kk];
                float a1 = As[m + 8][kk];
                float a2 = As[m][kk + 4];
                float a3 = As[m + 8][kk + 4];
                tf_split(a0, ah[mt][0], al[mt][0]);
                tf_split(a1, ah[mt][1], al[mt][1]);
                tf_split(a2, ah[mt][2], al[mt][2]);
                tf_split(a3, ah[mt][3], al[mt][3]);
            }
            // B fragments (2 n-tiles), split hi/lo
            unsigned bh[2][2], bl[2][2];
#pragma unroll
            for (int nt = 0; nt < 2; nt++) {
                int n = wn * 16 + nt * 8 + grp;
                float b0 = Bs[ks * 8 + tig][n];
                float b1 = Bs[ks * 8 + tig + 4][n];
                tf_split(b0, bh[nt][0], bl[nt][0]);
                tf_split(b1, bh[nt][1], bl[nt][1]);
            }
#pragma unroll
            for (int mt = 0; mt < 2; mt++)
#pragma unroll
                for (int nt = 0; nt < 2; nt++) {
                    float* d = acc[mt][nt];
                    mma_tf32(d, ah[mt][0], ah[mt][1], ah[mt][2], ah[mt][3],
                             bh[nt][0], bh[nt][1]);
                    mma_tf32(d, al[mt][0], al[mt][1], al[mt][2], al[mt][3],
                             bh[nt][0], bh[nt][1]);
                    mma_tf32(d, ah[mt][0], ah[mt][1], ah[mt][2], ah[mt][3],
                             bl[nt][0], bl[nt][1]);
                }
        }
        __syncthreads();
        if (more) {
            sstore();
            __syncthreads();
        }
    }

    // epilogue
#pragma unroll
    for (int mt = 0; mt < 2; mt++)
#pragma unroll
        for (int nt = 0; nt < 2; nt++)
#pragma unroll
            for (int r = 0; r < 4; r++) {
                int gm = bm + wm * 32 + mt * 16 + grp + (r >> 1) * 8;
                int gn = bn + wn * 16 + nt * 8 + tig * 2 + (r & 1);
                float v = acc[mt][nt][r];
                if (bias) v += bias[gn];
                if (act == 1) v = v / (1.f + __expf(-v));
                else if (act == 2) v = 1.f / (1.f + __expf(-v));
                if (mulp) v *= mulp[(long)gm * ldc + gn];
                if (resp) v += resp[(long)gm * ldc + gn];
                C[(long)gm * ldc + gn] = v;
            }
}

// ---------------- SIMT GEMM fallback (small N) ----------------
__global__ void gemm_k(const float* __restrict__ A, const float* __restrict__ Bm,
                       const float* __restrict__ bias, const float* __restrict__ mulb,
                       const float* __restrict__ resb, float* __restrict__ C,
                       int M, int N, int K, int lda, int ldb, int ldc,
                       long sA, long sB, long sC, int act) {
    int bz = blockIdx.z;
    A += (long)bz * sA;
    Bm += (long)bz * sB;
    C += (long)bz * sC;
    const float* mulp = mulb ? mulb + (long)bz * sC : nullptr;
    const float* resp = resb ? resb + (long)bz * sC : nullptr;

    int bm = blockIdx.y * 64, bn = blockIdx.x * 64;
    __shared__ float As[16][68];
    __shared__ float Bs[16][68];
    int tid = threadIdx.x;
    int ty = tid >> 4, tx = tid & 15;
    int aRow = tid >> 2;
    int aColBase = (tid & 3) * 4;
    int bRow = tid >> 4;
    int bColBase = (tid & 15) * 4;

    float acc[4][4];
#pragma unroll
    for (int i = 0; i < 4; i++)
#pragma unroll
        for (int j = 0; j < 4; j++) acc[i][j] = 0.f;

    for (int k0 = 0; k0 < K; k0 += 16) {
#pragma unroll
        for (int i = 0; i < 4; i++) {
            int kk = aColBase + i;
            int gm = bm + aRow, gk = k0 + kk;
            float val = (gm < M) ? A[(long)gm * lda + gk] : 0.f;
            As[kk][aRow] = val;
        }
#pragma unroll
        for (int i = 0; i < 4; i++) {
            int nn = bColBase + i;
            int gn = bn + nn, gk = k0 + bRow;
            float val = (gn < N) ? Bm[(long)gk * ldb + gn] : 0.f;
            Bs[bRow][nn] = val;
        }
        __syncthreads();
#pragma unroll
        for (int kk = 0; kk < 16; kk++) {
            float a[4], b[4];
#pragma unroll
            for (int i = 0; i < 4; i++) a[i] = As[kk][ty * 4 + i];
#pragma unroll
            for (int i = 0; i < 4; i++) b[i] = Bs[kk][tx * 4 + i];
#pragma unroll
            for (int i = 0; i < 4; i++)
#pragma unroll
                for (int j = 0; j < 4; j++) acc[i][j] += a[i] * b[j];
        }
        __syncthreads();
    }

#pragma unroll
    for (int i = 0; i < 4; i++) {
        int gm = bm + ty * 4 + i;
        if (gm >= M) continue;
#pragma unroll
        for (int j = 0; j < 4; j++) {
            int gn = bn + tx * 4 + j;
            if (gn >= N) continue;
            float v = acc[i][j];
            if (bias) v += bias[gn];
            if (act == 1) v = v / (1.f + __expf(-v));
            else if (act == 2) v = 1.f / (1.f + __expf(-v));
            if (mulp) v *= mulp[(long)gm * ldc + gn];
            if (resp) v += resp[(long)gm * ldc + gn];
            C[(long)gm * ldc + gn] = v;
        }
    }
}

// ---------------- group norm over 64 (l2norm or rmsnorm*w) ----------------
__global__ void groupnorm64_k(float* __restrict__ x, const float* __restrict__ w, int mode) {
    int g = blockIdx.x * 8 + (threadIdx.x >> 5);  // group over T*H
    int lane = threadIdx.x & 31;
    float* p = x + (size_t)g * 64;
    float a = p[lane], b = p[lane + 32];
    float s = a * a + b * b;
#pragma unroll
    for (int off = 16; off; off >>= 1) s += __shfl_xor_sync(0xffffffffu, s, off);
    float r = (mode == 0) ? rsqrtf(s + 1e-6f) : rsqrtf(s * (1.f / 64.f) + 1e-6f);
    float wa = mode ? w[lane] : 1.f;
    float wb = mode ? w[lane + 32] : 1.f;
    p[lane] = a * r * wa;
    p[lane + 32] = b * r * wb;
}

// ---------------- qk dot: qk[t,h] = dot(q[t,h,:], k[t,h,:]) ----------------
__global__ void qkdot_k(const float* __restrict__ q, const float* __restrict__ k,
                        float* __restrict__ qk) {
    int g = blockIdx.x * 8 + (threadIdx.x >> 5);  // over T*H
    int lane = threadIdx.x & 31;
    const float* qp = q + (size_t)g * 64;
    const float* kp = k + (size_t)g * 64;
    float s = qp[lane] * kp[lane] + qp[lane + 32] * kp[lane + 32];
#pragma unroll
    for (int off = 16; off; off >>= 1) s += __shfl_xor_sync(0xffffffffu, s, off);
    if (lane == 0) qk[g] = s;
}

// ---------------- row rmsnorm over D ----------------
__global__ void rmsnorm_row_k(const float* __restrict__ x, const float* __restrict__ w,
                              float* __restrict__ out) {
    int t = blockIdx.x;
    const float* p = x + (size_t)t * D;
    __shared__ float red[256];
    float s = 0.f;
    for (int i = threadIdx.x; i < D; i += 256) {
        float v = p[i];
        s += v * v;
    }
    red[threadIdx.x] = s;
    __syncthreads();
    for (int off = 128; off; off >>= 1) {
        if (threadIdx.x < off) red[threadIdx.x] += red[threadIdx.x + off];
        __syncthreads();
    }
    float r = rsqrtf(red[0] * (1.f / D) + 1e-6f);
    for (int i = threadIdx.x; i < D; i += 256)
        out[(size_t)t * D + i] = p[i] * r * w[i];
}

// ---------------- DeltaNet scan: barrier-free, warp-private smem ----------------
// One block per head, 256 threads = 8 warps. Warp w owns columns [8w, 8w+8).
// Thread (j', r): j = 8w + j', holds S[16r..16r+16, j] in registers.
// Each warp keeps its OWN double-buffered copy of (k,q,v-slice,beta,qk) in smem,
// filled by a 2-step-ahead LDG pipeline. Only __syncwarp per step, no __syncthreads.
// qk-trick: o_j = q.S_old[:,j] + (q.k) * delta_j  (exact).
__global__ void deltanet_scan_k(const float* __restrict__ q, const float* __restrict__ k,
                                const float* __restrict__ v, const float* __restrict__ beta,
                                const float* __restrict__ qk, float* __restrict__ o) {
    int h = blockIdx.x;
    int tid = threadIdx.x;
    int w = tid >> 5;
    int lane = tid & 31;
    int jp = lane >> 2;  // 0..7
    int r = lane & 3;

    // per-warp buffer: k[0..63], q[64..127], v[128..135], beta[136], qk[137]; pad to 144
    __shared__ float sbuf[8][2][144];

    const float* kh = k + h * 64;
    const float* qh = q + h * 64;
    const float* vh = v + h * 64 + 8 * w;

    float4 pA0, pA1, pB0, pB1;

    auto ldg_step = [&](int tt, float4& m0, float4& m1) {
        m0 = make_float4(0.f, 0.f, 0.f, 0.f);
        m1 = make_float4(0.f, 0.f, 0.f, 0.f);
        if (tt < T) {
            size_t off = (size_t)tt * D;
            if (lane < 16) m0 = *(const float4*)(kh + off + 4 * lane);
            else m0 = *(const float4*)(qh + off + 4 * (lane - 16));
            if (lane == 0) m1 = *(const float4*)(vh + off);
            else if (lane == 1) m1 = *(const float4*)(vh + off + 4);
            else if (lane == 2) m1.x = beta[tt * H + h];
            else if (lane == 3) m1.x = qk[tt * H + h];
        }
    };
    auto sts_step = [&](float* buf, const float4& m0, const float4& m1) {
        if (lane < 16) *(float4*)(buf + 4 * lane) = m0;
        else *(float4*)(buf + 64 + 4 * (lane - 16)) = m0;
        if (lane == 0) *(float4*)(buf + 128) = m1;
        else if (lane == 1) *(float4*)(buf + 132) = m1;
        else if (lane == 2) buf[136] = m1.x;
        else if (lane == 3) buf[137] = m1.x;
    };

    // prologue: stage t=0, preload t=1 into pendA
    ldg_step(0, pA0, pA1);
    sts_step(sbuf[w][0], pA0, pA1);
    ldg_step(1, pA0, pA1);
    __syncwarp();

    float s[16];
#pragma unroll
    for (int i = 0; i < 16; i++) s[i] = 0.f;

    for (int t = 0; t < T; t++) {
        ldg_step(t + 2, pB0, pB1);  // pendB: data for step t+2 (consumed at t+2)

        const float* cb = sbuf[w][t & 1];
        float kv[16], qv[16];
#pragma unroll
        for (int c = 0; c < 4; c++) {
            *(float4*)(kv + 4 * c) = *(const float4*)(cb + 16 * r + 4 * c);
            *(float4*)(qv + 4 * c) = *(const float4*)(cb + 64 + 16 * r + 4 * c);
        }
        float vj = cb[128 + jp];
        float bt = cb[136];
        float qkt = cb[137];

        // p = k.S[:,j], u = q.S[:,j]  (dual chains, then 4-lane reduce)
        float p0 = 0.f, p1 = 0.f, u0 = 0.f, u1 = 0.f;
#pragma unroll
        for (int i = 0; i < 16; i += 2) {
            p0 += kv[i] * s[i];
            p1 += kv[i + 1] * s[i + 1];
            u0 += qv[i] * s[i];
            u1 += qv[i + 1] * s[i + 1];
        }
        float p = p0 + p1, u = u0 + u1;
        p += __shfl_xor_sync(0xffffffffu, p, 1);
        u += __shfl_xor_sync(0xffffffffu, u, 1);
        p += __shfl_xor_sync(0xffffffffu, p, 2);
        u += __shfl_xor_sync(0xffffffffu, u, 2);

        float delta = bt * (vj - p);
        if (r == 0) o[(size_t)t * D + h * 64 + 8 * w + jp] = u + qkt * delta;

#pragma unroll
        for (int i = 0; i < 16; i++) s[i] += kv[i] * delta;

        // stage step t+1 data (pendA) into the other buffer; rotate pendB->pendA
        sts_step(sbuf[w][(t + 1) & 1], pA0, pA1);
        pA0 = pB0;
        pA1 = pB1;
        __syncwarp();
    }
}

// ---------------- attention scores: per-head tril(QK^T)/8 ----------------
__global__ void attn_scores_k(const float* __restrict__ q, const float* __restrict__ kk,
                              float* __restrict__ scores) {
    int h = blockIdx.z;
    int t0 = blockIdx.y * 32, s0 = blockIdx.x * 32;
    size_t base = (size_t)h * T * T;
    int tid = threadIdx.x;

    if (s0 > t0 + 31) {  // fully masked tile
        for (int idx = tid; idx < 1024; idx += 256) {
            int tt = idx >> 5, ss = idx & 31;
            scores[base + (size_t)(t0 + tt) * T + s0 + ss] = -1e30f;
        }
        return;
    }

    __shared__ float sQ[32][65], sK[32][65];
    for (int idx = tid; idx < 2048; idx += 256) {
        int rr = idx >> 6, cc = idx & 63;
        sQ[rr][cc] = q[(size_t)(t0 + rr) * D + h * 64 + cc];
        sK[rr][cc] = kk[(size_t)(s0 + rr) * D + h * 64 + cc];
    }
    __syncthreads();

    int sl = tid & 31, tg = tid >> 5;
#pragma unroll
    for (int i = 0; i < 4; i++) {
        int tt = tg + i * 8;
        float acc = 0.f;
#pragma unroll
        for (int d = 0; d < 64; d++) acc += sQ[tt][d] * sK[sl][d];
        int gt = t0 + tt, gs = s0 + sl;
        scores[base + (size_t)gt * T + gs] = (gs <= gt) ? acc * 0.125f : -1e30f;
    }
}

// ---------------- row softmax over 1024 ----------------
__global__ void softmax_k(float* __restrict__ scores) {
    size_t row = blockIdx.x;  // h*T + t
    float* p = scores + row * T;
    __shared__ float red[256];
    int tid = threadIdx.x;

    float v4[4];
    float m = -1e30f;
#pragma unroll
    for (int i = 0; i < 4; i++) {
        v4[i] = p[tid + i * 256];
        m = fmaxf(m, v4[i]);
    }
    red[tid] = m;
    __syncthreads();
    for (int off = 128; off; off >>= 1) {
        if (tid < off) red[tid] = fmaxf(red[tid], red[tid + off]);
        __syncthreads();
    }
    m = red[0];
    __syncthreads();

    float s = 0.f;
#pragma unroll
    for (int i = 0; i < 4; i++) {
        v4[i] = __expf(v4[i] - m);
        s += v4[i];
    }
    red[tid] = s;
    __syncthreads();
    for (int off = 128; off; off >>= 1) {
        if (tid < off) red[tid] += red[tid + off];
        __syncthreads();
    }
    float inv = 1.f / red[0];
#pragma unroll
    for (int i = 0; i < 4; i++) p[tid + i * 256] = v4[i] * inv;
}

// ---------------- host orchestration ----------------
static void launch_gemm(const float* A, const float* B, const float* bias, const float* mulb,
                        const float* resb, float* C, int M, int N, int K, int lda, int ldb,
                        int ldc, int act, int batch = 1, long sA = 0, long sB = 0, long sC = 0) {
    if ((M % 64 == 0) && (N % 64 == 0) && (K % 16 == 0)) {
        dim3 g(N / 64, M / 64, batch);
        tcgemm_k<<<g, 256>>>(A, B, bias, mulb, resb, C, M, N, K, lda, ldb, ldc, sA, sB, sC, act);
    } else {
        dim3 g((N + 63) / 64, (M + 63) / 64, batch);
        gemm_k<<<g, 256>>>(A, B, bias, mulb, resb, C, M, N, K, lda, ldb, ldc, sA, sB, sC, act);
    }
}

extern "C" void kernel_launch(void* const* d_in, const int* in_sizes, int n_in,
                              void* d_out, int out_size) {
    const int* ids = (const int*)d_in[0];
    const float* emb = (const float*)d_in[1];
    const float* enc_Wq = (const float*)d_in[2];
    const float* enc_Wk = (const float*)d_in[3];
    const float* enc_Wv = (const float*)d_in[4];
    const float* enc_Wb = (const float*)d_in[5];
    const float* enc_nw = (const float*)d_in[6];
    const float* enc_Wo = (const float*)d_in[7];
    const float* ck_W = (const float*)d_in[8];
    const float* ck_b = (const float*)d_in[9];
    const float* cv_W = (const float*)d_in[10];
    const float* cv_b = (const float*)d_in[11];
    const float* dn_Wq = (const float*)d_in[12];
    const float* dn_Wk = (const float*)d_in[13];
    const float* dn_Wv = (const float*)d_in[14];
    const float* dn_Wb = (const float*)d_in[15];
    const float* dn_nw = (const float*)d_in[16];
    const float* dn_Wo = (const float*)d_in[17];
    const float* sw_in_w = (const float*)d_in[18];
    const float* sw_post_w = (const float*)d_in[19];
    const float* sw_Wq = (const float*)d_in[20];
    const float* sw_Wo = (const float*)d_in[21];
    const float* sw_up_W = (const float*)d_in[22];
    const float* sw_up_b = (const float*)d_in[23];
    const float* sw_gate_W = (const float*)d_in[24];
    const float* sw_gate_b = (const float*)d_in[25];
    const float* sw_down_W = (const float*)d_in[26];
    const float* sw_down_b = (const float*)d_in[27];
    const float* final_w = (const float*)d_in[28];

    float *hs, *hbuf, *q, *k, *v, *beta, *qk, *o, *kc, *vc, *kcr, *scores, *ff1, *ff2, *ct, *st;
    cudaGetSymbolAddress((void**)&hs, g_hs);
    cudaGetSymbolAddress((void**)&hbuf, g_hbuf);
    cudaGetSymbolAddress((void**)&q, g_q);
    cudaGetSymbolAddress((void**)&k, g_k);
    cudaGetSymbolAddress((void**)&v, g_v);
    cudaGetSymbolAddress((void**)&beta, g_beta);
    cudaGetSymbolAddress((void**)&qk, g_qk);
    cudaGetSymbolAddress((void**)&o, g_o);
    cudaGetSymbolAddress((void**)&kc, g_kc);
    cudaGetSymbolAddress((void**)&vc, g_vc);
    cudaGetSymbolAddress((void**)&kcr, g_kcr);
    cudaGetSymbolAddress((void**)&scores, g_scores);
    cudaGetSymbolAddress((void**)&ff1, g_ff1);
    cudaGetSymbolAddress((void**)&ff2, g_ff2);
    cudaGetSymbolAddress((void**)&ct, g_cos);
    cudaGetSymbolAddress((void**)&st, g_sin);

    embed_k<<<T, 256>>>(ids, emb, hs);
    rope_tab_k<<<T, 32>>>(ct, st);

    auto deltanet = [&](const float* Wq, const float* Wk, const float* Wv, const float* Wb,
                        const float* nw, const float* Wo) {
        launch_gemm(hs, Wq, nullptr, nullptr, nullptr, q, T, D, D, D, D, D, 1);
        launch_gemm(hs, Wk, nullptr, nullptr, nullptr, k, T, D, D, D, D, D, 1);
        launch_gemm(hs, Wv, nullptr, nullptr, nullptr, v, T, D, D, D, D, D, 1);
        launch_gemm(hs, Wb, nullptr, nullptr, nullptr, beta, T, H, D, D, H, H, 2);
        groupnorm64_k<<<T * H / 8, 256>>>(q, nullptr, 0);
        groupnorm64_k<<<T * H / 8, 256>>>(k, nullptr, 0);
        qkdot_k<<<T * H / 8, 256>>>(q, k, qk);
        deltanet_scan_k<<<H, 256>>>(q, k, v, beta, qk, o);
        groupnorm64_k<<<T * H / 8, 256>>>(o, nw, 1);
        launch_gemm(o, Wo, nullptr, nullptr, nullptr, hs, T, D, D, D, D, D, 0);
    };

    for (int l = 0; l < 4; l++)
        deltanet(enc_Wq + (long)l * D * D, enc_Wk + (long)l * D * D, enc_Wv + (long)l * D * D,
                 enc_Wb + (long)l * D * H, enc_nw + (long)l * DHD, enc_Wo + (long)l * D * D);

    launch_gemm(hs, ck_W, ck_b, nullptr, nullptr, kc, T, D, D, D, D, D, 0);
    launch_gemm(hs, cv_W, cv_b, nullptr, nullptr, vc, T, D, D, D, D, D, 0);
    rope_apply_k<<<(T * H * 32 + 255) / 256, 256>>>(kc, kcr, ct, st);

    auto switcher = [&](int j) {
        rmsnorm_row_k<<<T, 256>>>(hs, sw_in_w + (long)j * D, hbuf);
        launch_gemm(hbuf, sw_Wq + (long)j * D * D, nullptr, nullptr, nullptr, q, T, D, D, D, D, D, 0);
        rope_apply_k<<<(T * H * 32 + 255) / 256, 256>>>(q, q, ct, st);
        attn_scores_k<<<dim3(T / 32, T / 32, H), 256>>>(q, kcr, scores);
        softmax_k<<<H * T, 256>>>(scores);
        launch_gemm(scores, vc, nullptr, nullptr, nullptr, o, T, DHD, T, T, D, D, 0,
                    H, (long)T * T, 64, 64);
        launch_gemm(o, sw_Wo + (long)j * D * D, nullptr, nullptr, hs, hs, T, D, D, D, D, D, 0);
        rmsnorm_row_k<<<T, 256>>>(hs, sw_post_w + (long)j * D, hbuf);
        launch_gemm(hbuf, sw_up_W + (long)j * D * DFF, sw_up_b + (long)j * DFF, nullptr, nullptr,
                    ff1, T, DFF, D, D, DFF, DFF, 0);
        launch_gemm(hbuf, sw_gate_W + (long)j * D * DFF, sw_gate_b + (long)j * DFF, ff1, nullptr,
                    ff2, T, DFF, D, D, DFF, DFF, 2);
        launch_gemm(ff2, sw_down_W + (long)j * DFF * D, sw_down_b + (long)j * D, nullptr, hs, hs,
                    T, D, DFF, DFF, D, D, 0);
    };

    switcher(0);
    deltanet(dn_Wq, dn_Wk, dn_Wv, dn_Wb, dn_nw, dn_Wo);
    switcher(1);
    deltanet(dn_Wq + (long)D * D, dn_Wk + (long)D * D, dn_Wv + (long)D * D,
             dn_Wb + (long)D * H, dn_nw + DHD, dn_Wo + (long)D * D);

    rmsnorm_row_k<<<T, 256>>>(hs, final_w, (float*)d_out);
}

// round 9
// speedup vs baseline: 1.4796x; 1.4796x over previous
#include <cuda_runtime.h>
#include <cuda_bf16.h>

#define T 1024
#define D 1024
#define H 16
#define DHD 64
#define DFF 4096

// ---------------- static scratch (device globals; no allocation) ----------------
__device__ float g_hs[T * D];
__device__ float g_hbuf[T * D];
__device__ float g_q[T * D];
__device__ float g_k[T * D];
__device__ float g_v[T * D];
__device__ float g_beta[T * H];
__device__ float g_o[T * D];
__device__ float g_kc[T * D];
__device__ float g_vc[T * D];
__device__ float g_kcr[T * D];
__device__ float g_scores[(size_t)H * T * T];
__device__ float g_ff1[T * DFF];
__device__ float g_ff2[T * DFF];
__device__ float g_cos[T * 32];
__device__ float g_sin[T * 32];

// ---------------- embedding gather ----------------
__global__ void embed_k(const int* __restrict__ ids, const float* __restrict__ emb,
                        float* __restrict__ out) {
    int t = blockIdx.x;
    int id = ids[t];
    for (int i = threadIdx.x; i < D; i += 256)
        out[(size_t)t * D + i] = emb[(size_t)id * D + i];
}

// ---------------- rope tables ----------------
__global__ void rope_tab_k(float* __restrict__ ct, float* __restrict__ st) {
    int t = blockIdx.x, i = threadIdx.x;  // i in [0,32)
    float inv = __powf(10000.0f, -(float)i / 32.0f);
    float f = (float)t * inv;
    ct[t * 32 + i] = cosf(f);
    st[t * 32 + i] = sinf(f);
}

// rope apply on [T, H, 64]; in may equal out
__global__ void rope_apply_k(const float* __restrict__ in, float* __restrict__ out,
                             const float* __restrict__ ct, const float* __restrict__ st) {
    int idx = blockIdx.x * 256 + threadIdx.x;  // T*H*32 total
    if (idx >= T * H * 32) return;
    int d = idx & 31;
    int th = idx >> 5;
    int h = th & (H - 1);
    int t = th >> 4;
    float c = ct[t * 32 + d], s = st[t * 32 + d];
    const float* pi = in + (size_t)t * D + h * DHD;
    float* po = out + (size_t)t * D + h * DHD;
    float x0 = pi[d], x1 = pi[d + 32];
    po[d] = x0 * c - x1 * s;
    po[d + 32] = x1 * c + x0 * s;
}

// ---------------- bf16 split helpers ----------------
// pair (x0 at k, x1 at k+1) -> (hi bf16x2 [low=x0hi], lo bf16x2 [low=x0lo])
__device__ __forceinline__ uint2 bfsplit2(float x0, float x1) {
    unsigned hi;
    asm("prmt.b32 %0, %1, %2, 0x7632;"
        : "=r"(hi) : "r"(__float_as_uint(x0)), "r"(__float_as_uint(x1)));
    float h0 = __uint_as_float(__float_as_uint(x0) & 0xFFFF0000u);
    float h1 = __uint_as_float(__float_as_uint(x1) & 0xFFFF0000u);
    unsigned lo;
    asm("cvt.rn.bf16x2.f32 %0, %1, %2;" : "=r"(lo) : "f"(x1 - h1), "f"(x0 - h0));
    return make_uint2(hi, lo);
}
__device__ __forceinline__ void mma_bf16(float* d, unsigned a0, unsigned a1, unsigned a2,
                                         unsigned a3, unsigned b0, unsigned b1) {
    asm volatile(
        "mma.sync.aligned.m16n8k16.row.col.f32.bf16.bf16.f32 "
        "{%0,%1,%2,%3}, {%4,%5,%6,%7}, {%8,%9}, {%0,%1,%2,%3};"
        : "+f"(d[0]), "+f"(d[1]), "+f"(d[2]), "+f"(d[3])
        : "r"(a0), "r"(a1), "r"(a2), "r"(a3), "r"(b0), "r"(b1));
}

// ---------------- tensor-core GEMM (3xBF16, hi/lo pre-split packed in smem) ----------------
// C = act(A@B + bias) [*mul] [+res].  Requires M%64==0, N%64==0, K%16==0.
// 64x64x16 tile, 256 threads = 8 warps in 2x4 grid, warp tile 32x16. R3 loop skeleton.
__global__ __launch_bounds__(256) void tcgemm_k(
        const float* __restrict__ A, const float* __restrict__ Bm,
        const float* __restrict__ bias, const float* __restrict__ mulb,
        const float* __restrict__ resb, float* __restrict__ C,
        int M, int N, int K, int lda, int ldb, int ldc,
        long sA, long sB, long sC, int act) {
    int bz = blockIdx.z;
    A += (long)bz * sA;
    Bm += (long)bz * sB;
    C += (long)bz * sC;
    const float* mulp = mulb ? mulb + (long)bz * sC : nullptr;
    const float* resp = resb ? resb + (long)bz * sC : nullptr;

    int bm = blockIdx.y * 64, bn = blockIdx.x * 64;

    // [row][kpair] uint2 = (hi bf16x2, lo bf16x2); kpair 0..7 used, padded to 12 (stride 24 words)
    __shared__ uint2 Asp[64][12];
    __shared__ uint2 Bsp[64][12];

    int tid = threadIdx.x;
    int lane = tid & 31;
    int warp = tid >> 5;
    int wm = warp >> 2;   // 0..1 -> rows wm*32
    int wn = warp & 3;    // 0..3 -> cols wn*16
    int grp = lane >> 2;  // 0..7
    int tig = lane & 3;   // 0..3

    // staging maps
    int arow = tid >> 2;            // 0..63
    int atig = tid & 3;             // kpairs atig, atig+4
    int bkp = lane >> 2;            // 0..7
    int bn0 = warp * 8 + (lane & 3);  // n and n+4

    float2 a01, a89;
    float bx0, bx1, bx2, bx3;
    auto gload = [&](int k0) {
        const float* ap = A + (long)(bm + arow) * lda + k0;
        a01 = *(const float2*)(ap + 2 * atig);
        a89 = *(const float2*)(ap + 2 * atig + 8);
        const float* bp = Bm + (long)(k0 + 2 * bkp) * ldb + bn;
        bx0 = bp[bn0];
        bx1 = bp[ldb + bn0];
        bx2 = bp[bn0 + 4];
        bx3 = bp[ldb + bn0 + 4];
    };
    auto sstore = [&]() {
        Asp[arow][atig] = bfsplit2(a01.x, a01.y);
        Asp[arow][atig + 4] = bfsplit2(a89.x, a89.y);
        Bsp[bn0][bkp] = bfsplit2(bx0, bx1);
        Bsp[bn0 + 4][bkp] = bfsplit2(bx2, bx3);
    };

    float acc[2][2][4];
#pragma unroll
    for (int i = 0; i < 2; i++)
#pragma unroll
        for (int j = 0; j < 2; j++)
#pragma unroll
            for (int r = 0; r < 4; r++) acc[i][j][r] = 0.f;

    gload(0);
    sstore();
    __syncthreads();

    for (int k0 = 0; k0 < K; k0 += 16) {
        bool more = (k0 + 16) < K;
        if (more) gload(k0 + 16);

        uint2 aE[2][4];
#pragma unroll
        for (int mt = 0; mt < 2; mt++) {
            int m = wm * 32 + mt * 16 + grp;
            aE[mt][0] = Asp[m][tig];
            aE[mt][1] = Asp[m + 8][tig];
            aE[mt][2] = Asp[m][tig + 4];
            aE[mt][3] = Asp[m + 8][tig + 4];
        }
        uint2 bE[2][2];
#pragma unroll
        for (int nt = 0; nt < 2; nt++) {
            int n = wn * 16 + nt * 8 + grp;
            bE[nt][0] = Bsp[n][tig];
            bE[nt][1] = Bsp[n][tig + 4];
        }
#pragma unroll
        for (int mt = 0; mt < 2; mt++)
#pragma unroll
            for (int nt = 0; nt < 2; nt++) {
                float* d = acc[mt][nt];
                mma_bf16(d, aE[mt][0].x, aE[mt][1].x, aE[mt][2].x, aE[mt][3].x,
                         bE[nt][0].x, bE[nt][1].x);  // hi*hi
                mma_bf16(d, aE[mt][0].y, aE[mt][1].y, aE[mt][2].y, aE[mt][3].y,
                         bE[nt][0].x, bE[nt][1].x);  // lo*hi
                mma_bf16(d, aE[mt][0].x, aE[mt][1].x, aE[mt][2].x, aE[mt][3].x,
                         bE[nt][0].y, bE[nt][1].y);  // hi*lo
            }
        __syncthreads();
        if (more) {
            sstore();
            __syncthreads();
        }
    }

    // epilogue (same fragment->C mapping as m16n8 D layout)
#pragma unroll
    for (int mt = 0; mt < 2; mt++)
#pragma unroll
        for (int nt = 0; nt < 2; nt++)
#pragma unroll
            for (int r = 0; r < 4; r++) {
                int gm = bm + wm * 32 + mt * 16 + grp + (r >> 1) * 8;
                int gn = bn + wn * 16 + nt * 8 + tig * 2 + (r & 1);
                float v = acc[mt][nt][r];
                if (bias) v += bias[gn];
                if (act == 1) v = v / (1.f + __expf(-v));
                else if (act == 2) v = 1.f / (1.f + __expf(-v));
                if (mulp) v *= mulp[(long)gm * ldc + gn];
                if (resp) v += resp[(long)gm * ldc + gn];
                C[(long)gm * ldc + gn] = v;
            }
}

// ---------------- SIMT GEMM fallback (small N) ----------------
__global__ void gemm_k(const float* __restrict__ A, const float* __restrict__ Bm,
                       const float* __restrict__ bias, const float* __restrict__ mulb,
                       const float* __restrict__ resb, float* __restrict__ C,
                       int M, int N, int K, int lda, int ldb, int ldc,
                       long sA, long sB, long sC, int act) {
    int bz = blockIdx.z;
    A += (long)bz * sA;
    Bm += (long)bz * sB;
    C += (long)bz * sC;
    const float* mulp = mulb ? mulb + (long)bz * sC : nullptr;
    const float* resp = resb ? resb + (long)bz * sC : nullptr;

    int bm = blockIdx.y * 64, bn = blockIdx.x * 64;
    __shared__ float As[16][68];
    __shared__ float Bs[16][68];
    int tid = threadIdx.x;
    int ty = tid >> 4, tx = tid & 15;
    int aRow = tid >> 2;
    int aColBase = (tid & 3) * 4;
    int bRow = tid >> 4;
    int bColBase = (tid & 15) * 4;

    float acc[4][4];
#pragma unroll
    for (int i = 0; i < 4; i++)
#pragma unroll
        for (int j = 0; j < 4; j++) acc[i][j] = 0.f;

    for (int k0 = 0; k0 < K; k0 += 16) {
#pragma unroll
        for (int i = 0; i < 4; i++) {
            int kk = aColBase + i;
            int gm = bm + aRow, gk = k0 + kk;
            float val = (gm < M) ? A[(long)gm * lda + gk] : 0.f;
            As[kk][aRow] = val;
        }
#pragma unroll
        for (int i = 0; i < 4; i++) {
            int nn = bColBase + i;
            int gn = bn + nn, gk = k0 + bRow;
            float val = (gn < N) ? Bm[(long)gk * ldb + gn] : 0.f;
            Bs[bRow][nn] = val;
        }
        __syncthreads();
#pragma unroll
        for (int kk = 0; kk < 16; kk++) {
            float a[4], b[4];
#pragma unroll
            for (int i = 0; i < 4; i++) a[i] = As[kk][ty * 4 + i];
#pragma unroll
            for (int i = 0; i < 4; i++) b[i] = Bs[kk][tx * 4 + i];
#pragma unroll
            for (int i = 0; i < 4; i++)
#pragma unroll
                for (int j = 0; j < 4; j++) acc[i][j] += a[i] * b[j];
        }
        __syncthreads();
    }

#pragma unroll
    for (int i = 0; i < 4; i++) {
        int gm = bm + ty * 4 + i;
        if (gm >= M) continue;
#pragma unroll
        for (int j = 0; j < 4; j++) {
            int gn = bn + tx * 4 + j;
            if (gn >= N) continue;
            float v = acc[i][j];
            if (bias) v += bias[gn];
            if (act == 1) v = v / (1.f + __expf(-v));
            else if (act == 2) v = 1.f / (1.f + __expf(-v));
            if (mulp) v *= mulp[(long)gm * ldc + gn];
            if (resp) v += resp[(long)gm * ldc + gn];
            C[(long)gm * ldc + gn] = v;
        }
    }
}

// ---------------- group norm over 64 (l2norm or rmsnorm*w) ----------------
__global__ void groupnorm64_k(float* __restrict__ x, const float* __restrict__ w, int mode) {
    int g = blockIdx.x * 8 + (threadIdx.x >> 5);  // group over T*H
    int lane = threadIdx.x & 31;
    float* p = x + (size_t)g * 64;
    float a = p[lane], b = p[lane + 32];
    float s = a * a + b * b;
#pragma unroll
    for (int off = 16; off; off >>= 1) s += __shfl_xor_sync(0xffffffffu, s, off);
    float r = (mode == 0) ? rsqrtf(s + 1e-6f) : rsqrtf(s * (1.f / 64.f) + 1e-6f);
    float wa = mode ? w[lane] : 1.f;
    float wb = mode ? w[lane + 32] : 1.f;
    p[lane] = a * r * wa;
    p[lane + 32] = b * r * wb;
}

// ---------------- row rmsnorm over D ----------------
__global__ void rmsnorm_row_k(const float* __restrict__ x, const float* __restrict__ w,
                              float* __restrict__ out) {
    int t = blockIdx.x;
    const float* p = x + (size_t)t * D;
    __shared__ float red[256];
    float s = 0.f;
    for (int i = threadIdx.x; i < D; i += 256) {
        float v = p[i];
        s += v * v;
    }
    red[threadIdx.x] = s;
    __syncthreads();
    for (int off = 128; off; off >>= 1) {
        if (threadIdx.x < off) red[threadIdx.x] += red[threadIdx.x + off];
        __syncthreads();
    }
    float r = rsqrtf(red[0] * (1.f / D) + 1e-6f);
    for (int i = threadIdx.x; i < D; i += 256)
        out[(size_t)t * D + i] = p[i] * r * w[i];
}

// ---------------- DeltaNet sequential scan (R3 original) ----------------
__global__ void deltanet_scan_k(const float* __restrict__ q, const float* __restrict__ k,
                                const float* __restrict__ v, const float* __restrict__ beta,
                                float* __restrict__ o) {
    int h = blockIdx.x;
    int tid = threadIdx.x;
    int j = tid >> 2;
    int r = tid & 3;
    __shared__ float sk[2][64], sq[2][64], sv[2][64], sb[2];

    float s[16];
#pragma unroll
    for (int i = 0; i < 16; i++) s[i] = 0.f;

    if (tid < 64) sk[0][tid] = k[(size_t)h * 64 + tid];
    else if (tid < 128) sq[0][tid - 64] = q[(size_t)h * 64 + (tid - 64)];
    else if (tid < 192) sv[0][tid - 128] = v[(size_t)h * 64 + (tid - 128)];
    else if (tid == 192) sb[0] = beta[h];
    __syncthreads();

    for (int t = 0; t < T; t++) {
        int cur = t & 1, nxt = cur ^ 1;
        float pre = 0.f;
        bool havePre = (t + 1 < T) && (tid <= 192);
        if (havePre) {
            int tt = t + 1;
            if (tid < 64) pre = k[(size_t)tt * D + h * 64 + tid];
            else if (tid < 128) pre = q[(size_t)tt * D + h * 64 + (tid - 64)];
            else if (tid < 192) pre = v[(size_t)tt * D + h * 64 + (tid - 128)];
            else pre = beta[tt * H + h];
        }

        float p0 = 0.f, p1 = 0.f;
#pragma unroll
        for (int i = 0; i < 16; i += 2) {
            p0 += sk[cur][r * 16 + i] * s[i];
            p1 += sk[cur][r * 16 + i + 1] * s[i + 1];
        }
        float p = p0 + p1;
        p += __shfl_xor_sync(0xffffffffu, p, 1);
        p += __shfl_xor_sync(0xffffffffu, p, 2);

        float delta = sb[cur] * (sv[cur][j] - p);

        float o0 = 0.f, o1 = 0.f;
#pragma unroll
        for (int i = 0; i < 16; i += 2) {
            s[i] += sk[cur][r * 16 + i] * delta;
            o0 += sq[cur][r * 16 + i] * s[i];
            s[i + 1] += sk[cur][r * 16 + i + 1] * delta;
            o1 += sq[cur][r * 16 + i + 1] * s[i + 1];
        }
        float oo = o0 + o1;
        oo += __shfl_xor_sync(0xffffffffu, oo, 1);
        oo += __shfl_xor_sync(0xffffffffu, oo, 2);
        if (r == 0) o[(size_t)t * D + h * 64 + j] = oo;

        if (havePre) {
            if (tid < 64) sk[nxt][tid] = pre;
            else if (tid < 128) sq[nxt][tid - 64] = pre;
            else if (tid < 192) sv[nxt][tid - 128] = pre;
            else sb[nxt] = pre;
        }
        __syncthreads();
    }
}

// ---------------- attention scores: per-head tril(QK^T)/8 ----------------
__global__ void attn_scores_k(const float* __restrict__ q, const float* __restrict__ kk,
                              float* __restrict__ scores) {
    int h = blockIdx.z;
    int t0 = blockIdx.y * 32, s0 = blockIdx.x * 32;
    size_t base = (size_t)h * T * T;
    int tid = threadIdx.x;

    if (s0 > t0 + 31) {  // fully masked tile
        for (int idx = tid; idx < 1024; idx += 256) {
            int tt = idx >> 5, ss = idx & 31;
            scores[base + (size_t)(t0 + tt) * T + s0 + ss] = -1e30f;
        }
        return;
    }

    __shared__ float sQ[32][65], sK[32][65];
    for (int idx = tid; idx < 2048; idx += 256) {
        int rr = idx >> 6, cc = idx & 63;
        sQ[rr][cc] = q[(size_t)(t0 + rr) * D + h * 64 + cc];
        sK[rr][cc] = kk[(size_t)(s0 + rr) * D + h * 64 + cc];
    }
    __syncthreads();

    int sl = tid & 31, tg = tid >> 5;
#pragma unroll
    for (int i = 0; i < 4; i++) {
        int tt = tg + i * 8;
        float acc = 0.f;
#pragma unroll
        for (int d = 0; d < 64; d++) acc += sQ[tt][d] * sK[sl][d];
        int gt = t0 + tt, gs = s0 + sl;
        scores[base + (size_t)gt * T + gs] = (gs <= gt) ? acc * 0.125f : -1e30f;
    }
}

// ---------------- row softmax over 1024 ----------------
__global__ void softmax_k(float* __restrict__ scores) {
    size_t row = blockIdx.x;  // h*T + t
    float* p = scores + row * T;
    __shared__ float red[256];
    int tid = threadIdx.x;

    float v4[4];
    float m = -1e30f;
#pragma unroll
    for (int i = 0; i < 4; i++) {
        v4[i] = p[tid + i * 256];
        m = fmaxf(m, v4[i]);
    }
    red[tid] = m;
    __syncthreads();
    for (int off = 128; off; off >>= 1) {
        if (tid < off) red[tid] = fmaxf(red[tid], red[tid + off]);
        __syncthreads();
    }
    m = red[0];
    __syncthreads();

    float s = 0.f;
#pragma unroll
    for (int i = 0; i < 4; i++) {
        v4[i] = __expf(v4[i] - m);
        s += v4[i];
    }
    red[tid] = s;
    __syncthreads();
    for (int off = 128; off; off >>= 1) {
        if (tid < off) red[tid] += red[tid + off];
        __syncthreads();
    }
    float inv = 1.f / red[0];
#pragma unroll
    for (int i = 0; i < 4; i++) p[tid + i * 256] = v4[i] * inv;
}

// ---------------- host orchestration ----------------
static void launch_gemm(const float* A, const float* B, const float* bias, const float* mulb,
                        const float* resb, float* C, int M, int N, int K, int lda, int ldb,
                        int ldc, int act, int batch = 1, long sA = 0, long sB = 0, long sC = 0) {
    if ((M % 64 == 0) && (N % 64 == 0) && (K % 16 == 0)) {
        dim3 g(N / 64, M / 64, batch);
        tcgemm_k<<<g, 256>>>(A, B, bias, mulb, resb, C, M, N, K, lda, ldb, ldc, sA, sB, sC, act);
    } else {
        dim3 g((N + 63) / 64, (M + 63) / 64, batch);
        gemm_k<<<g, 256>>>(A, B, bias, mulb, resb, C, M, N, K, lda, ldb, ldc, sA, sB, sC, act);
    }
}

extern "C" void kernel_launch(void* const* d_in, const int* in_sizes, int n_in,
                              void* d_out, int out_size) {
    const int* ids = (const int*)d_in[0];
    const float* emb = (const float*)d_in[1];
    const float* enc_Wq = (const float*)d_in[2];
    const float* enc_Wk = (const float*)d_in[3];
    const float* enc_Wv = (const float*)d_in[4];
    const float* enc_Wb = (const float*)d_in[5];
    const float* enc_nw = (const float*)d_in[6];
    const float* enc_Wo = (const float*)d_in[7];
    const float* ck_W = (const float*)d_in[8];
    const float* ck_b = (const float*)d_in[9];
    const float* cv_W = (const float*)d_in[10];
    const float* cv_b = (const float*)d_in[11];
    const float* dn_Wq = (const float*)d_in[12];
    const float* dn_Wk = (const float*)d_in[13];
    const float* dn_Wv = (const float*)d_in[14];
    const float* dn_Wb = (const float*)d_in[15];
    const float* dn_nw = (const float*)d_in[16];
    const float* dn_Wo = (const float*)d_in[17];
    const float* sw_in_w = (const float*)d_in[18];
    const float* sw_post_w = (const float*)d_in[19];
    const float* sw_Wq = (const float*)d_in[20];
    const float* sw_Wo = (const float*)d_in[21];
    const float* sw_up_W = (const float*)d_in[22];
    const float* sw_up_b = (const float*)d_in[23];
    const float* sw_gate_W = (const float*)d_in[24];
    const float* sw_gate_b = (const float*)d_in[25];
    const float* sw_down_W = (const float*)d_in[26];
    const float* sw_down_b = (const float*)d_in[27];
    const float* final_w = (const float*)d_in[28];

    float *hs, *hbuf, *q, *k, *v, *beta, *o, *kc, *vc, *kcr, *scores, *ff1, *ff2, *ct, *st;
    cudaGetSymbolAddress((void**)&hs, g_hs);
    cudaGetSymbolAddress((void**)&hbuf, g_hbuf);
    cudaGetSymbolAddress((void**)&q, g_q);
    cudaGetSymbolAddress((void**)&k, g_k);
    cudaGetSymbolAddress((void**)&v, g_v);
    cudaGetSymbolAddress((void**)&beta, g_beta);
    cudaGetSymbolAddress((void**)&o, g_o);
    cudaGetSymbolAddress((void**)&kc, g_kc);
    cudaGetSymbolAddress((void**)&vc, g_vc);
    cudaGetSymbolAddress((void**)&kcr, g_kcr);
    cudaGetSymbolAddress((void**)&scores, g_scores);
    cudaGetSymbolAddress((void**)&ff1, g_ff1);
    cudaGetSymbolAddress((void**)&ff2, g_ff2);
    cudaGetSymbolAddress((void**)&ct, g_cos);
    cudaGetSymbolAddress((void**)&st, g_sin);

    embed_k<<<T, 256>>>(ids, emb, hs);
    rope_tab_k<<<T, 32>>>(ct, st);

    auto deltanet = [&](const float* Wq, const float* Wk, const float* Wv, const float* Wb,
                        const float* nw, const float* Wo) {
        launch_gemm(hs, Wq, nullptr, nullptr, nullptr, q, T, D, D, D, D, D, 1);
        launch_gemm(hs, Wk, nullptr, nullptr, nullptr, k, T, D, D, D, D, D, 1);
        launch_gemm(hs, Wv, nullptr, nullptr, nullptr, v, T, D, D, D, D, D, 1);
        launch_gemm(hs, Wb, nullptr, nullptr, nullptr, beta, T, H, D, D, H, H, 2);
        groupnorm64_k<<<T * H / 8, 256>>>(q, nullptr, 0);
        groupnorm64_k<<<T * H / 8, 256>>>(k, nullptr, 0);
        deltanet_scan_k<<<H, 256>>>(q, k, v, beta, o);
        groupnorm64_k<<<T * H / 8, 256>>>(o, nw, 1);
        launch_gemm(o, Wo, nullptr, nullptr, nullptr, hs, T, D, D, D, D, D, 0);
    };

    for (int l = 0; l < 4; l++)
        deltanet(enc_Wq + (long)l * D * D, enc_Wk + (long)l * D * D, enc_Wv + (long)l * D * D,
                 enc_Wb + (long)l * D * H, enc_nw + (long)l * DHD, enc_Wo + (long)l * D * D);

    launch_gemm(hs, ck_W, ck_b, nullptr, nullptr, kc, T, D, D, D, D, D, 0);
    launch_gemm(hs, cv_W, cv_b, nullptr, nullptr, vc, T, D, D, D, D, D, 0);
    rope_apply_k<<<(T * H * 32 + 255) / 256, 256>>>(kc, kcr, ct, st);

    auto switcher = [&](int j) {
        rmsnorm_row_k<<<T, 256>>>(hs, sw_in_w + (long)j * D, hbuf);
        launch_gemm(hbuf, sw_Wq + (long)j * D * D, nullptr, nullptr, nullptr, q, T, D, D, D, D, D, 0);
        rope_apply_k<<<(T * H * 32 + 255) / 256, 256>>>(q, q, ct, st);
        attn_scores_k<<<dim3(T / 32, T / 32, H), 256>>>(q, kcr, scores);
        softmax_k<<<H * T, 256>>>(scores);
        launch_gemm(scores, vc, nullptr, nullptr, nullptr, o, T, DHD, T, T, D, D, 0,
                    H, (long)T * T, 64, 64);
        launch_gemm(o, sw_Wo + (long)j * D * D, nullptr, nullptr, hs, hs, T, D, D, D, D, D, 0);
        rmsnorm_row_k<<<T, 256>>>(hs, sw_post_w + (long)j * D, hbuf);
        launch_gemm(hbuf, sw_up_W + (long)j * D * DFF, sw_up_b + (long)j * DFF, nullptr, nullptr,
                    ff1, T, DFF, D, D, DFF, DFF, 0);
        launch_gemm(hbuf, sw_gate_W + (long)j * D * DFF, sw_gate_b + (long)j * DFF, ff1, nullptr,
                    ff2, T, DFF, D, D, DFF, DFF, 2);
        launch_gemm(ff2, sw_down_W + (long)j * DFF * D, sw_down_b + (long)j * D, nullptr, hs, hs,
                    T, D, DFF, DFF, D, D, 0);
    };

    switcher(0);
    deltanet(dn_Wq, dn_Wk, dn_Wv, dn_Wb, dn_nw, dn_Wo);
    switcher(1);
    deltanet(dn_Wq + (long)D * D, dn_Wk + (long)D * D, dn_Wv + (long)D * D,
             dn_Wb + (long)D * H, dn_nw + DHD, dn_Wo + (long)D * D);

    rmsnorm_row_k<<<T, 256>>>(hs, final_w, (float*)d_out);
}

// round 10
// speedup vs baseline: 1.5624x; 1.0560x over previous
#include <cuda_runtime.h>
#include <cuda_bf16.h>

#define T 1024
#define D 1024
#define H 16
#define DHD 64
#define DFF 4096

// ---------------- static scratch (device globals; no allocation) ----------------
__device__ float g_hs[T * D];
__device__ float g_hbuf[T * D];
__device__ float g_q[T * D];
__device__ float g_k[T * D];
__device__ float g_v[T * D];
__device__ float g_beta[T * H];
__device__ float g_o[T * D];
__device__ float g_kc[T * D];
__device__ float g_vc[T * D];
__device__ float g_kcr[T * D];
__device__ float g_scores[(size_t)H * T * T];
__device__ float g_ff1[T * DFF];
__device__ float g_ff2[T * DFF];
__device__ float g_cos[T * 32];
__device__ float g_sin[T * 32];
__device__ uint2 g_asp[(size_t)H * T * T / 2];  // pre-split A (max: scores)
__device__ uint2 g_bsp[(size_t)D * DFF / 2];    // pre-split B (max: up/gate W)

// ---------------- embedding gather ----------------
__global__ void embed_k(const int* __restrict__ ids, const float* __restrict__ emb,
                        float* __restrict__ out) {
    int t = blockIdx.x;
    int id = ids[t];
    for (int i = threadIdx.x; i < D; i += 256)
        out[(size_t)t * D + i] = emb[(size_t)id * D + i];
}

// ---------------- rope tables ----------------
__global__ void rope_tab_k(float* __restrict__ ct, float* __restrict__ st) {
    int t = blockIdx.x, i = threadIdx.x;  // i in [0,32)
    float inv = __powf(10000.0f, -(float)i / 32.0f);
    float f = (float)t * inv;
    ct[t * 32 + i] = cosf(f);
    st[t * 32 + i] = sinf(f);
}

// rope apply on [T, H, 64]; in may equal out
__global__ void rope_apply_k(const float* __restrict__ in, float* __restrict__ out,
                             const float* __restrict__ ct, const float* __restrict__ st) {
    int idx = blockIdx.x * 256 + threadIdx.x;  // T*H*32 total
    if (idx >= T * H * 32) return;
    int d = idx & 31;
    int th = idx >> 5;
    int h = th & (H - 1);
    int t = th >> 4;
    float c = ct[t * 32 + d], s = st[t * 32 + d];
    const float* pi = in + (size_t)t * D + h * DHD;
    float* po = out + (size_t)t * D + h * DHD;
    float x0 = pi[d], x1 = pi[d + 32];
    po[d] = x0 * c - x1 * s;
    po[d + 32] = x1 * c + x0 * s;
}

// ---------------- bf16 RN split: pair (x0,x1) -> (hi bf16x2 [low=x0], lo bf16x2) ----------------
__device__ __forceinline__ uint2 bfsplit2_rn(float x0, float x1) {
    unsigned hi;
    asm("cvt.rn.bf16x2.f32 %0, %1, %2;" : "=r"(hi) : "f"(x1), "f"(x0));
    float h0 = __uint_as_float(hi << 16);
    float h1 = __uint_as_float(hi & 0xFFFF0000u);
    unsigned lo;
    asm("cvt.rn.bf16x2.f32 %0, %1, %2;" : "=r"(lo) : "f"(x1 - h1), "f"(x0 - h0));
    return make_uint2(hi, lo);
}

// A-style pre-split: row-major [M][K], adjacent-k pairs. npairs = M*K/2.
__global__ void presplitA_k(const float* __restrict__ in, uint2* __restrict__ out, int npairs) {
    int i = blockIdx.x * 256 + threadIdx.x;
    if (i >= npairs) return;
    float2 v = ((const float2*)in)[i];
    out[i] = bfsplit2_rn(v.x, v.y);
}

// B-style pre-split: [K][N] row-major, pairs rows (2p, 2p+1). out[p*N + n].
__global__ void presplitB_k(const float* __restrict__ in, uint2* __restrict__ out,
                            int Kd, int Nd) {
    int i = blockIdx.x * 256 + threadIdx.x;
    if (i >= (Kd / 2) * Nd) return;
    int n = i % Nd, p = i / Nd;
    out[i] = bfsplit2_rn(in[(size_t)(2 * p) * Nd + n], in[(size_t)(2 * p + 1) * Nd + n]);
}

__device__ __forceinline__ void mma_bf16(float* d, unsigned a0, unsigned a1, unsigned a2,
                                         unsigned a3, unsigned b0, unsigned b1) {
    asm volatile(
        "mma.sync.aligned.m16n8k16.row.col.f32.bf16.bf16.f32 "
        "{%0,%1,%2,%3}, {%4,%5,%6,%7}, {%8,%9}, {%0,%1,%2,%3};"
        : "+f"(d[0]), "+f"(d[1]), "+f"(d[2]), "+f"(d[3])
        : "r"(a0), "r"(a1), "r"(a2), "r"(a3), "r"(b0), "r"(b1));
}

// ---------------- tensor-core GEMM (3xBF16, operands pre-split in global) ----------------
// C = act(A@B + bias) [*mul] [+res].  A: [M][Kp] uint2 pairs; B: [Kp][N] uint2 pairs.
// 64x64xKp8 tile, 256 threads = 8 warps in 2x4 grid, warp tile 32x16. R9 loop skeleton.
__global__ __launch_bounds__(256) void tcgemm_k(
        const uint2* __restrict__ A, const uint2* __restrict__ B,
        const float* __restrict__ bias, const float* __restrict__ mulb,
        const float* __restrict__ resb, float* __restrict__ C,
        int M, int N, int Kp, int ldap, int ldb, int ldc,
        long sAp, long sBp, long sC, int act) {
    int bz = blockIdx.z;
    A += (long)bz * sAp;
    B += (long)bz * sBp;
    C += (long)bz * sC;
    const float* mulp = mulb ? mulb + (long)bz * sC : nullptr;
    const float* resp = resb ? resb + (long)bz * sC : nullptr;

    int bm = blockIdx.y * 64, bn = blockIdx.x * 64;

    // [row][kpair] uint2 = (hi bf16x2, lo bf16x2); kpair 0..7, padded to 12 (24 words)
    __shared__ uint2 Asp[64][12];
    __shared__ uint2 Bsp[64][12];

    int tid = threadIdx.x;
    int lane = tid & 31;
    int warp = tid >> 5;
    int wm = warp >> 2;   // 0..1 -> rows wm*32
    int wn = warp & 3;    // 0..3 -> cols wn*16
    int grp = lane >> 2;  // 0..7
    int tig = lane & 3;   // 0..3

    // staging maps
    int arow = tid >> 2;              // 0..63
    int atig = tid & 3;               // kpairs atig, atig+4
    int bkp = lane >> 2;              // 0..7
    int bn0 = warp * 8 + (lane & 3);  // n and n+4

    uint2 aU0, aU1, bU0, bU1;
    auto gload = [&](int kp0) {
        const uint2* ap = A + (long)(bm + arow) * ldap + kp0;
        aU0 = ap[atig];
        aU1 = ap[atig + 4];
        const uint2* bp = B + (long)(kp0 + bkp) * ldb + bn;
        bU0 = bp[bn0];
        bU1 = bp[bn0 + 4];
    };
    auto sstore = [&]() {
        Asp[arow][atig] = aU0;
        Asp[arow][atig + 4] = aU1;
        Bsp[bn0][bkp] = bU0;
        Bsp[bn0 + 4][bkp] = bU1;
    };

    float acc[2][2][4];
#pragma unroll
    for (int i = 0; i < 2; i++)
#pragma unroll
        for (int j = 0; j < 2; j++)
#pragma unroll
            for (int r = 0; r < 4; r++) acc[i][j][r] = 0.f;

    gload(0);
    sstore();
    __syncthreads();

    for (int kp0 = 0; kp0 < Kp; kp0 += 8) {
        bool more = (kp0 + 8) < Kp;
        if (more) gload(kp0 + 8);

        uint2 aE[2][4];
#pragma unroll
        for (int mt = 0; mt < 2; mt++) {
            int m = wm * 32 + mt * 16 + grp;
            aE[mt][0] = Asp[m][tig];
            aE[mt][1] = Asp[m + 8][tig];
            aE[mt][2] = Asp[m][tig + 4];
            aE[mt][3] = Asp[m + 8][tig + 4];
        }
        uint2 bE[2][2];
#pragma unroll
        for (int nt = 0; nt < 2; nt++) {
            int n = wn * 16 + nt * 8 + grp;
            bE[nt][0] = Bsp[n][tig];
            bE[nt][1] = Bsp[n][tig + 4];
        }
#pragma unroll
        for (int mt = 0; mt < 2; mt++)
#pragma unroll
            for (int nt = 0; nt < 2; nt++) {
                float* d = acc[mt][nt];
                mma_bf16(d, aE[mt][0].x, aE[mt][1].x, aE[mt][2].x, aE[mt][3].x,
                         bE[nt][0].x, bE[nt][1].x);  // hi*hi
                mma_bf16(d, aE[mt][0].y, aE[mt][1].y, aE[mt][2].y, aE[mt][3].y,
                         bE[nt][0].x, bE[nt][1].x);  // lo*hi
                mma_bf16(d, aE[mt][0].x, aE[mt][1].x, aE[mt][2].x, aE[mt][3].x,
                         bE[nt][0].y, bE[nt][1].y);  // hi*lo
            }
        __syncthreads();
        if (more) {
            sstore();
            __syncthreads();
        }
    }

    // epilogue (m16n8 D fragment layout)
#pragma unroll
    for (int mt = 0; mt < 2; mt++)
#pragma unroll
        for (int nt = 0; nt < 2; nt++)
#pragma unroll
            for (int r = 0; r < 4; r++) {
                int gm = bm + wm * 32 + mt * 16 + grp + (r >> 1) * 8;
                int gn = bn + wn * 16 + nt * 8 + tig * 2 + (r & 1);
                float v = acc[mt][nt][r];
                if (bias) v += bias[gn];
                if (act == 1) v = v / (1.f + __expf(-v));
                else if (act == 2) v = 1.f / (1.f + __expf(-v));
                if (mulp) v *= mulp[(long)gm * ldc + gn];
                if (resp) v += resp[(long)gm * ldc + gn];
                C[(long)gm * ldc + gn] = v;
            }
}

// ---------------- SIMT GEMM fallback (small N; float inputs) ----------------
__global__ void gemm_k(const float* __restrict__ A, const float* __restrict__ Bm,
                       const float* __restrict__ bias, const float* __restrict__ mulb,
                       const float* __restrict__ resb, float* __restrict__ C,
                       int M, int N, int K, int lda, int ldb, int ldc,
                       long sA, long sB, long sC, int act) {
    int bz = blockIdx.z;
    A += (long)bz * sA;
    Bm += (long)bz * sB;
    C += (long)bz * sC;
    const float* mulp = mulb ? mulb + (long)bz * sC : nullptr;
    const float* resp = resb ? resb + (long)bz * sC : nullptr;

    int bm = blockIdx.y * 64, bn = blockIdx.x * 64;
    __shared__ float As[16][68];
    __shared__ float Bs[16][68];
    int tid = threadIdx.x;
    int ty = tid >> 4, tx = tid & 15;
    int aRow = tid >> 2;
    int aColBase = (tid & 3) * 4;
    int bRow = tid >> 4;
    int bColBase = (tid & 15) * 4;

    float acc[4][4];
#pragma unroll
    for (int i = 0; i < 4; i++)
#pragma unroll
        for (int j = 0; j < 4; j++) acc[i][j] = 0.f;

    for (int k0 = 0; k0 < K; k0 += 16) {
#pragma unroll
        for (int i = 0; i < 4; i++) {
            int kk = aColBase + i;
            int gm = bm + aRow, gk = k0 + kk;
            float val = (gm < M) ? A[(long)gm * lda + gk] : 0.f;
            As[kk][aRow] = val;
        }
#pragma unroll
        for (int i = 0; i < 4; i++) {
            int nn = bColBase + i;
            int gn = bn + nn, gk = k0 + bRow;
            float val = (gn < N) ? Bm[(long)gk * ldb + gn] : 0.f;
            Bs[bRow][nn] = val;
        }
        __syncthreads();
#pragma unroll
        for (int kk = 0; kk < 16; kk++) {
            float a[4], b[4];
#pragma unroll
            for (int i = 0; i < 4; i++) a[i] = As[kk][ty * 4 + i];
#pragma unroll
            for (int i = 0; i < 4; i++) b[i] = Bs[kk][tx * 4 + i];
#pragma unroll
            for (int i = 0; i < 4; i++)
#pragma unroll
                for (int j = 0; j < 4; j++) acc[i][j] += a[i] * b[j];
        }
        __syncthreads();
    }

#pragma unroll
    for (int i = 0; i < 4; i++) {
        int gm = bm + ty * 4 + i;
        if (gm >= M) continue;
#pragma unroll
        for (int j = 0; j < 4; j++) {
            int gn = bn + tx * 4 + j;
            if (gn >= N) continue;
            float v = acc[i][j];
            if (bias) v += bias[gn];
            if (act == 1) v = v / (1.f + __expf(-v));
            else if (act == 2) v = 1.f / (1.f + __expf(-v));
            if (mulp) v *= mulp[(long)gm * ldc + gn];
            if (resp) v += resp[(long)gm * ldc + gn];
            C[(long)gm * ldc + gn] = v;
        }
    }
}

// ---------------- group norm over 64 (l2norm or rmsnorm*w) ----------------
__global__ void groupnorm64_k(float* __restrict__ x, const float* __restrict__ w, int mode) {
    int g = blockIdx.x * 8 + (threadIdx.x >> 5);  // group over T*H
    int lane = threadIdx.x & 31;
    float* p = x + (size_t)g * 64;
    float a = p[lane], b = p[lane + 32];
    float s = a * a + b * b;
#pragma unroll
    for (int off = 16; off; off >>= 1) s += __shfl_xor_sync(0xffffffffu, s, off);
    float r = (mode == 0) ? rsqrtf(s + 1e-6f) : rsqrtf(s * (1.f / 64.f) + 1e-6f);
    float wa = mode ? w[lane] : 1.f;
    float wb = mode ? w[lane + 32] : 1.f;
    p[lane] = a * r * wa;
    p[lane + 32] = b * r * wb;
}

// ---------------- row rmsnorm over D ----------------
__global__ void rmsnorm_row_k(const float* __restrict__ x, const float* __restrict__ w,
                              float* __restrict__ out) {
    int t = blockIdx.x;
    const float* p = x + (size_t)t * D;
    __shared__ float red[256];
    float s = 0.f;
    for (int i = threadIdx.x; i < D; i += 256) {
        float v = p[i];
        s += v * v;
    }
    red[threadIdx.x] = s;
    __syncthreads();
    for (int off = 128; off; off >>= 1) {
        if (threadIdx.x < off) red[threadIdx.x] += red[threadIdx.x + off];
        __syncthreads();
    }
    float r = rsqrtf(red[0] * (1.f / D) + 1e-6f);
    for (int i = threadIdx.x; i < D; i += 256)
        out[(size_t)t * D + i] = p[i] * r * w[i];
}

// ---------------- DeltaNet sequential scan (R3 original) ----------------
__global__ void deltanet_scan_k(const float* __restrict__ q, const float* __restrict__ k,
                                const float* __restrict__ v, const float* __restrict__ beta,
                                float* __restrict__ o) {
    int h = blockIdx.x;
    int tid = threadIdx.x;
    int j = tid >> 2;
    int r = tid & 3;
    __shared__ float sk[2][64], sq[2][64], sv[2][64], sb[2];

    float s[16];
#pragma unroll
    for (int i = 0; i < 16; i++) s[i] = 0.f;

    if (tid < 64) sk[0][tid] = k[(size_t)h * 64 + tid];
    else if (tid < 128) sq[0][tid - 64] = q[(size_t)h * 64 + (tid - 64)];
    else if (tid < 192) sv[0][tid - 128] = v[(size_t)h * 64 + (tid - 128)];
    else if (tid == 192) sb[0] = beta[h];
    __syncthreads();

    for (int t = 0; t < T; t++) {
        int cur = t & 1, nxt = cur ^ 1;
        float pre = 0.f;
        bool havePre = (t + 1 < T) && (tid <= 192);
        if (havePre) {
            int tt = t + 1;
            if (tid < 64) pre = k[(size_t)tt * D + h * 64 + tid];
            else if (tid < 128) pre = q[(size_t)tt * D + h * 64 + (tid - 64)];
            else if (tid < 192) pre = v[(size_t)tt * D + h * 64 + (tid - 128)];
            else pre = beta[tt * H + h];
        }

        float p0 = 0.f, p1 = 0.f;
#pragma unroll
        for (int i = 0; i < 16; i += 2) {
            p0 += sk[cur][r * 16 + i] * s[i];
            p1 += sk[cur][r * 16 + i + 1] * s[i + 1];
        }
        float p = p0 + p1;
        p += __shfl_xor_sync(0xffffffffu, p, 1);
        p += __shfl_xor_sync(0xffffffffu, p, 2);

        float delta = sb[cur] * (sv[cur][j] - p);

        float o0 = 0.f, o1 = 0.f;
#pragma unroll
        for (int i = 0; i < 16; i += 2) {
            s[i] += sk[cur][r * 16 + i] * delta;
            o0 += sq[cur][r * 16 + i] * s[i];
            s[i + 1] += sk[cur][r * 16 + i + 1] * delta;
            o1 += sq[cur][r * 16 + i + 1] * s[i + 1];
        }
        float oo = o0 + o1;
        oo += __shfl_xor_sync(0xffffffffu, oo, 1);
        oo += __shfl_xor_sync(0xffffffffu, oo, 2);
        if (r == 0) o[(size_t)t * D + h * 64 + j] = oo;

        if (havePre) {
            if (tid < 64) sk[nxt][tid] = pre;
            else if (tid < 128) sq[nxt][tid - 64] = pre;
            else if (tid < 192) sv[nxt][tid - 128] = pre;
            else sb[nxt] = pre;
        }
        __syncthreads();
    }
}

// ---------------- attention scores: per-head tril(QK^T)/8 ----------------
__global__ void attn_scores_k(const float* __restrict__ q, const float* __restrict__ kk,
                              float* __restrict__ scores) {
    int h = blockIdx.z;
    int t0 = blockIdx.y * 32, s0 = blockIdx.x * 32;
    size_t base = (size_t)h * T * T;
    int tid = threadIdx.x;

    if (s0 > t0 + 31) {  // fully masked tile
        for (int idx = tid; idx < 1024; idx += 256) {
            int tt = idx >> 5, ss = idx & 31;
            scores[base + (size_t)(t0 + tt) * T + s0 + ss] = -1e30f;
        }
        return;
    }

    __shared__ float sQ[32][65], sK[32][65];
    for (int idx = tid; idx < 2048; idx += 256) {
        int rr = idx >> 6, cc = idx & 63;
        sQ[rr][cc] = q[(size_t)(t0 + rr) * D + h * 64 + cc];
        sK[rr][cc] = kk[(size_t)(s0 + rr) * D + h * 64 + cc];
    }
    __syncthreads();

    int sl = tid & 31, tg = tid >> 5;
#pragma unroll
    for (int i = 0; i < 4; i++) {
        int tt = tg + i * 8;
        float acc = 0.f;
#pragma unroll
        for (int d = 0; d < 64; d++) acc += sQ[tt][d] * sK[sl][d];
        int gt = t0 + tt, gs = s0 + sl;
        scores[base + (size_t)gt * T + gs] = (gs <= gt) ? acc * 0.125f : -1e30f;
    }
}

// ---------------- row softmax over 1024 ----------------
__global__ void softmax_k(float* __restrict__ scores) {
    size_t row = blockIdx.x;  // h*T + t
    float* p = scores + row * T;
    __shared__ float red[256];
    int tid = threadIdx.x;

    float v4[4];
    float m = -1e30f;
#pragma unroll
    for (int i = 0; i < 4; i++) {
        v4[i] = p[tid + i * 256];
        m = fmaxf(m, v4[i]);
    }
    red[tid] = m;
    __syncthreads();
    for (int off = 128; off; off >>= 1) {
        if (tid < off) red[tid] = fmaxf(red[tid], red[tid + off]);
        __syncthreads();
    }
    m = red[0];
    __syncthreads();

    float s = 0.f;
#pragma unroll
    for (int i = 0; i < 4; i++) {
        v4[i] = __expf(v4[i] - m);
        s += v4[i];
    }
    red[tid] = s;
    __syncthreads();
    for (int off = 128; off; off >>= 1) {
        if (tid < off) red[tid] += red[tid + off];
        __syncthreads();
    }
    float inv = 1.f / red[0];
#pragma unroll
    for (int i = 0; i < 4; i++) p[tid + i * 256] = v4[i] * inv;
}

// ---------------- host orchestration ----------------
static uint2 *s_asp, *s_bsp;

static void presplitA(const float* src, int nElts) {
    presplitA_k<<<(nElts / 2 + 255) / 256, 256>>>(src, s_asp, nElts / 2);
}
static void presplitB(const float* src, int K, int N) {
    presplitB_k<<<((K / 2) * N + 255) / 256, 256>>>(src, s_bsp, K, N);
}
// tcgemm on pre-split operands. K in floats; lda in floats (pairs = lda/2).
static void tc_gemm(const float* bias, const float* mulb, const float* resb, float* C,
                    int M, int N, int K, int ldb, int ldc, int act,
                    int batch = 1, long sApairs = 0, long sBpairs = 0, long sC = 0,
                    int ldapairs = -1) {
    if (ldapairs < 0) ldapairs = K / 2;
    dim3 g(N / 64, M / 64, batch);
    tcgemm_k<<<g, 256>>>(s_asp, s_bsp, bias, mulb, resb, C, M, N, K / 2, ldapairs, ldb, ldc,
                         sApairs, sBpairs, sC, act);
}

extern "C" void kernel_launch(void* const* d_in, const int* in_sizes, int n_in,
                              void* d_out, int out_size) {
    const int* ids = (const int*)d_in[0];
    const float* emb = (const float*)d_in[1];
    const float* enc_Wq = (const float*)d_in[2];
    const float* enc_Wk = (const float*)d_in[3];
    const float* enc_Wv = (const float*)d_in[4];
    const float* enc_Wb = (const float*)d_in[5];
    const float* enc_nw = (const float*)d_in[6];
    const float* enc_Wo = (const float*)d_in[7];
    const float* ck_W = (const float*)d_in[8];
    const float* ck_b = (const float*)d_in[9];
    const float* cv_W = (const float*)d_in[10];
    const float* cv_b = (const float*)d_in[11];
    const float* dn_Wq = (const float*)d_in[12];
    const float* dn_Wk = (const float*)d_in[13];
    const float* dn_Wv = (const float*)d_in[14];
    const float* dn_Wb = (const float*)d_in[15];
    const float* dn_nw = (const float*)d_in[16];
    const float* dn_Wo = (const float*)d_in[17];
    const float* sw_in_w = (const float*)d_in[18];
    const float* sw_post_w = (const float*)d_in[19];
    const float* sw_Wq = (const float*)d_in[20];
    const float* sw_Wo = (const float*)d_in[21];
    const float* sw_up_W = (const float*)d_in[22];
    const float* sw_up_b = (const float*)d_in[23];
    const float* sw_gate_W = (const float*)d_in[24];
    const float* sw_gate_b = (const float*)d_in[25];
    const float* sw_down_W = (const float*)d_in[26];
    const float* sw_down_b = (const float*)d_in[27];
    const float* final_w = (const float*)d_in[28];

    float *hs, *hbuf, *q, *k, *v, *beta, *o, *kc, *vc, *kcr, *scores, *ff1, *ff2, *ct, *st;
    cudaGetSymbolAddress((void**)&hs, g_hs);
    cudaGetSymbolAddress((void**)&hbuf, g_hbuf);
    cudaGetSymbolAddress((void**)&q, g_q);
    cudaGetSymbolAddress((void**)&k, g_k);
    cudaGetSymbolAddress((void**)&v, g_v);
    cudaGetSymbolAddress((void**)&beta, g_beta);
    cudaGetSymbolAddress((void**)&o, g_o);
    cudaGetSymbolAddress((void**)&kc, g_kc);
    cudaGetSymbolAddress((void**)&vc, g_vc);
    cudaGetSymbolAddress((void**)&kcr, g_kcr);
    cudaGetSymbolAddress((void**)&scores, g_scores);
    cudaGetSymbolAddress((void**)&ff1, g_ff1);
    cudaGetSymbolAddress((void**)&ff2, g_ff2);
    cudaGetSymbolAddress((void**)&ct, g_cos);
    cudaGetSymbolAddress((void**)&st, g_sin);
    cudaGetSymbolAddress((void**)&s_asp, g_asp);
    cudaGetSymbolAddress((void**)&s_bsp, g_bsp);

    embed_k<<<T, 256>>>(ids, emb, hs);
    rope_tab_k<<<T, 32>>>(ct, st);

    auto deltanet = [&](const float* Wq, const float* Wk, const float* Wv, const float* Wb,
                        const float* nw, const float* Wo) {
        presplitA(hs, T * D);  // hs split once for q/k/v
        presplitB(Wq, D, D);
        tc_gemm(nullptr, nullptr, nullptr, q, T, D, D, D, D, 1);
        presplitB(Wk, D, D);
        tc_gemm(nullptr, nullptr, nullptr, k, T, D, D, D, D, 1);
        presplitB(Wv, D, D);
        tc_gemm(nullptr, nullptr, nullptr, v, T, D, D, D, D, 1);
        // beta: small-N SIMT path on raw floats
        {
            dim3 g((H + 63) / 64, T / 64, 1);
            gemm_k<<<g, 256>>>(hs, Wb, nullptr, nullptr, nullptr, beta, T, H, D, D, H, H,
                               0, 0, 0, 2);
        }
        groupnorm64_k<<<T * H / 8, 256>>>(q, nullptr, 0);
        groupnorm64_k<<<T * H / 8, 256>>>(k, nullptr, 0);
        deltanet_scan_k<<<H, 256>>>(q, k, v, beta, o);
        groupnorm64_k<<<T * H / 8, 256>>>(o, nw, 1);
        presplitA(o, T * D);
        presplitB(Wo, D, D);
        tc_gemm(nullptr, nullptr, nullptr, hs, T, D, D, D, D, 0);
    };

    for (int l = 0; l < 4; l++)
        deltanet(enc_Wq + (long)l * D * D, enc_Wk + (long)l * D * D, enc_Wv + (long)l * D * D,
                 enc_Wb + (long)l * D * H, enc_nw + (long)l * DHD, enc_Wo + (long)l * D * D);

    presplitA(hs, T * D);
    presplitB(ck_W, D, D);
    tc_gemm(ck_b, nullptr, nullptr, kc, T, D, D, D, D, 0);
    presplitB(cv_W, D, D);
    tc_gemm(cv_b, nullptr, nullptr, vc, T, D, D, D, D, 0);
    rope_apply_k<<<(T * H * 32 + 255) / 256, 256>>>(kc, kcr, ct, st);

    auto switcher = [&](int j) {
        rmsnorm_row_k<<<T, 256>>>(hs, sw_in_w + (long)j * D, hbuf);
        presplitA(hbuf, T * D);
        presplitB(sw_Wq + (long)j * D * D, D, D);
        tc_gemm(nullptr, nullptr, nullptr, q, T, D, D, D, D, 0);
        rope_apply_k<<<(T * H * 32 + 255) / 256, 256>>>(q, q, ct, st);
        attn_scores_k<<<dim3(T / 32, T / 32, H), 256>>>(q, kcr, scores);
        softmax_k<<<H * T, 256>>>(scores);
        // att @ V, batched over heads: A = scores [H][T][T], B = vc column slices
        presplitA(scores, H * T * T);
        presplitB(vc, T, D);
        tc_gemm(nullptr, nullptr, nullptr, o, T, DHD, T, D, D, 0,
                H, (long)T * T / 2, 64, 64);
        presplitA(o, T * D);
        presplitB(sw_Wo + (long)j * D * D, D, D);
        tc_gemm(nullptr, nullptr, hs, hs, T, D, D, D, D, 0);
        rmsnorm_row_k<<<T, 256>>>(hs, sw_post_w + (long)j * D, hbuf);
        presplitA(hbuf, T * D);
        presplitB(sw_up_W + (long)j * D * DFF, D, DFF);
        tc_gemm(sw_up_b + (long)j * DFF, nullptr, nullptr, ff1, T, DFF, D, DFF, DFF, 0);
        presplitB(sw_gate_W + (long)j * D * DFF, D, DFF);
        tc_gemm(sw_gate_b + (long)j * DFF, ff1, nullptr, ff2, T, DFF, D, DFF, DFF, 2);
        presplitA(ff2, T * DFF);
        presplitB(sw_down_W + (long)j * DFF * D, DFF, D);
        tc_gemm(sw_down_b + (long)j * D, nullptr, hs, hs, T, D, DFF, D, D, 0);
    };

    switcher(0);
    deltanet(dn_Wq, dn_Wk, dn_Wv, dn_Wb, dn_nw, dn_Wo);
    switcher(1);
    deltanet(dn_Wq + (long)D * D, dn_Wk + (long)D * D, dn_Wv + (long)D * D,
             dn_Wb + (long)D * H, dn_nw + DHD, dn_Wo + (long)D * D);

    rmsnorm_row_k<<<T, 256>>>(hs, final_w, (float*)d_out);
}

// round 11
// speedup vs baseline: 1.5830x; 1.0132x over previous
#include <cuda_runtime.h>
#include <cuda_bf16.h>

#define T 1024
#define D 1024
#define H 16
#define DHD 64
#define DFF 4096

// ---------------- static scratch (device globals; no allocation) ----------------
__device__ float g_hs[T * D];
__device__ float g_hbuf[T * D];
__device__ float g_q[T * D];
__device__ float g_k[T * D];
__device__ float g_v[T * D];
__device__ float g_beta[T * H];
__device__ float g_o[T * D];
__device__ float g_kc[T * D];
__device__ float g_vc[T * D];
__device__ float g_kcr[T * D];
__device__ float g_scores[(size_t)H * T * T];
__device__ float g_ff1[T * DFF];
__device__ float g_ff2[T * DFF];
__device__ float g_cos[T * 32];
__device__ float g_sin[T * 32];
__device__ uint2 g_asp[(size_t)H * T * T / 2];  // pre-split A (max: scores)
__device__ uint2 g_bsp[(size_t)D * DFF / 2];    // pre-split B (max: up/gate W)
__device__ uint2 g_ktp[32 * H * T];             // pre-split K^T pairs [32][H*T]
__device__ uint2 g_vcp[(T / 2) * D];            // pre-split vc pairs [T/2][D]

// ---------------- embedding gather ----------------
__global__ void embed_k(const int* __restrict__ ids, const float* __restrict__ emb,
                        float* __restrict__ out) {
    int t = blockIdx.x;
    int id = ids[t];
    for (int i = threadIdx.x; i < D; i += 256)
        out[(size_t)t * D + i] = emb[(size_t)id * D + i];
}

// ---------------- rope tables ----------------
__global__ void rope_tab_k(float* __restrict__ ct, float* __restrict__ st) {
    int t = blockIdx.x, i = threadIdx.x;  // i in [0,32)
    float inv = __powf(10000.0f, -(float)i / 32.0f);
    float f = (float)t * inv;
    ct[t * 32 + i] = cosf(f);
    st[t * 32 + i] = sinf(f);
}

// rope apply on [T, H, 64]; in may equal out
__global__ void rope_apply_k(const float* __restrict__ in, float* __restrict__ out,
                             const float* __restrict__ ct, const float* __restrict__ st) {
    int idx = blockIdx.x * 256 + threadIdx.x;  // T*H*32 total
    if (idx >= T * H * 32) return;
    int d = idx & 31;
    int th = idx >> 5;
    int h = th & (H - 1);
    int t = th >> 4;
    float c = ct[t * 32 + d], s = st[t * 32 + d];
    const float* pi = in + (size_t)t * D + h * DHD;
    float* po = out + (size_t)t * D + h * DHD;
    float x0 = pi[d], x1 = pi[d + 32];
    po[d] = x0 * c - x1 * s;
    po[d + 32] = x1 * c + x0 * s;
}

// ---------------- bf16 RN split: pair (x0,x1) -> (hi bf16x2 [low=x0], lo bf16x2) ------------
__device__ __forceinline__ uint2 bfsplit2_rn(float x0, float x1) {
    unsigned hi;
    asm("cvt.rn.bf16x2.f32 %0, %1, %2;" : "=r"(hi) : "f"(x1), "f"(x0));
    float h0 = __uint_as_float(hi << 16);
    float h1 = __uint_as_float(hi & 0xFFFF0000u);
    unsigned lo;
    asm("cvt.rn.bf16x2.f32 %0, %1, %2;" : "=r"(lo) : "f"(x1 - h1), "f"(x0 - h0));
    return make_uint2(hi, lo);
}

// A-style pre-split: row-major [M][K], adjacent-k pairs. npairs = M*K/2.
__global__ void presplitA_k(const float* __restrict__ in, uint2* __restrict__ out, int npairs) {
    int i = blockIdx.x * 256 + threadIdx.x;
    if (i >= npairs) return;
    float2 v = ((const float2*)in)[i];
    out[i] = bfsplit2_rn(v.x, v.y);
}

// B-style pre-split: [K][N] row-major, pairs rows (2p, 2p+1). out[p*N + n].
__global__ void presplitB_k(const float* __restrict__ in, uint2* __restrict__ out,
                            int Kd, int Nd) {
    int i = blockIdx.x * 256 + threadIdx.x;
    if (i >= (Kd / 2) * Nd) return;
    int n = i % Nd, p = i / Nd;
    out[i] = bfsplit2_rn(in[(size_t)(2 * p) * Nd + n], in[(size_t)(2 * p + 1) * Nd + n]);
}

// K^T pre-split: kcr [T][H*64] -> out[p][h*T + s] = split(kcr[s][h*64+2p], kcr[s][h*64+2p+1])
__global__ void presplitKT_k(const float* __restrict__ in, uint2* __restrict__ out) {
    int h = blockIdx.y;
    int s0 = blockIdx.x * 32;
    __shared__ float sm[32][65];
    int tid = threadIdx.x;
    for (int idx = tid; idx < 32 * 64; idx += 256) {
        int rr = idx >> 6, cc = idx & 63;
        sm[rr][cc] = in[(size_t)(s0 + rr) * D + h * 64 + cc];
    }
    __syncthreads();
    for (int idx = tid; idx < 1024; idx += 256) {
        int p = idx >> 5, sp = idx & 31;
        out[(size_t)p * (H * T) + h * T + s0 + sp] = bfsplit2_rn(sm[sp][2 * p], sm[sp][2 * p + 1]);
    }
}

__device__ __forceinline__ void mma_bf16(float* d, unsigned a0, unsigned a1, unsigned a2,
                                         unsigned a3, unsigned b0, unsigned b1) {
    asm volatile(
        "mma.sync.aligned.m16n8k16.row.col.f32.bf16.bf16.f32 "
        "{%0,%1,%2,%3}, {%4,%5,%6,%7}, {%8,%9}, {%0,%1,%2,%3};"
        : "+f"(d[0]), "+f"(d[1]), "+f"(d[2]), "+f"(d[3])
        : "r"(a0), "r"(a1), "r"(a2), "r"(a3), "r"(b0), "r"(b1));
}

// ---------------- tensor-core GEMM (3xBF16, operands pre-split in global) ----------------
// C = act(A@B + bias) [*mul] [+res].  A: [M][Kp] uint2 pairs; B: [Kp][N] uint2 pairs.
// act: 0 none, 1 silu, 2 sigmoid, 3 causal-mask (*0.125 if gn<=gm else -1e30)
__global__ __launch_bounds__(256) void tcgemm_k(
        const uint2* __restrict__ A, const uint2* __restrict__ B,
        const float* __restrict__ bias, const float* __restrict__ mulb,
        const float* __restrict__ resb, float* __restrict__ C,
        int M, int N, int Kp, int ldap, int ldb, int ldc,
        long sAp, long sBp, long sC, int act) {
    int bz = blockIdx.z;
    A += (long)bz * sAp;
    B += (long)bz * sBp;
    C += (long)bz * sC;
    const float* mulp = mulb ? mulb + (long)bz * sC : nullptr;
    const float* resp = resb ? resb + (long)bz * sC : nullptr;

    int bm = blockIdx.y * 64, bn = blockIdx.x * 64;

    __shared__ uint2 Asp[64][12];
    __shared__ uint2 Bsp[64][12];

    int tid = threadIdx.x;
    int lane = tid & 31;
    int warp = tid >> 5;
    int wm = warp >> 2;   // 0..1 -> rows wm*32
    int wn = warp & 3;    // 0..3 -> cols wn*16
    int grp = lane >> 2;  // 0..7
    int tig = lane & 3;   // 0..3

    // staging maps
    int arow = tid >> 2;              // 0..63
    int atig = tid & 3;               // kpairs atig, atig+4
    int bkp = lane >> 2;              // 0..7
    int bn0 = warp * 8 + (lane & 3);  // n and n+4

    uint2 aU0, aU1, bU0, bU1;
    auto gload = [&](int kp0) {
        const uint2* ap = A + (long)(bm + arow) * ldap + kp0;
        aU0 = ap[atig];
        aU1 = ap[atig + 4];
        const uint2* bp = B + (long)(kp0 + bkp) * ldb + bn;
        bU0 = bp[bn0];
        bU1 = bp[bn0 + 4];
    };
    auto sstore = [&]() {
        Asp[arow][atig] = aU0;
        Asp[arow][atig + 4] = aU1;
        Bsp[bn0][bkp] = bU0;
        Bsp[bn0 + 4][bkp] = bU1;
    };

    float acc[2][2][4];
#pragma unroll
    for (int i = 0; i < 2; i++)
#pragma unroll
        for (int j = 0; j < 2; j++)
#pragma unroll
            for (int r = 0; r < 4; r++) acc[i][j][r] = 0.f;

    gload(0);
    sstore();
    __syncthreads();

    for (int kp0 = 0; kp0 < Kp; kp0 += 8) {
        bool more = (kp0 + 8) < Kp;
        if (more) gload(kp0 + 8);

        uint2 aE[2][4];
#pragma unroll
        for (int mt = 0; mt < 2; mt++) {
            int m = wm * 32 + mt * 16 + grp;
            aE[mt][0] = Asp[m][tig];
            aE[mt][1] = Asp[m + 8][tig];
            aE[mt][2] = Asp[m][tig + 4];
            aE[mt][3] = Asp[m + 8][tig + 4];
        }
        uint2 bE[2][2];
#pragma unroll
        for (int nt = 0; nt < 2; nt++) {
            int n = wn * 16 + nt * 8 + grp;
            bE[nt][0] = Bsp[n][tig];
            bE[nt][1] = Bsp[n][tig + 4];
        }
#pragma unroll
        for (int mt = 0; mt < 2; mt++)
#pragma unroll
            for (int nt = 0; nt < 2; nt++) {
                float* d = acc[mt][nt];
                mma_bf16(d, aE[mt][0].x, aE[mt][1].x, aE[mt][2].x, aE[mt][3].x,
                         bE[nt][0].x, bE[nt][1].x);  // hi*hi
                mma_bf16(d, aE[mt][0].y, aE[mt][1].y, aE[mt][2].y, aE[mt][3].y,
                         bE[nt][0].x, bE[nt][1].x);  // lo*hi
                mma_bf16(d, aE[mt][0].x, aE[mt][1].x, aE[mt][2].x, aE[mt][3].x,
                         bE[nt][0].y, bE[nt][1].y);  // hi*lo
            }
        __syncthreads();
        if (more) {
            sstore();
            __syncthreads();
        }
    }

    // epilogue (m16n8 D fragment layout)
#pragma unroll
    for (int mt = 0; mt < 2; mt++)
#pragma unroll
        for (int nt = 0; nt < 2; nt++)
#pragma unroll
            for (int r = 0; r < 4; r++) {
                int gm = bm + wm * 32 + mt * 16 + grp + (r >> 1) * 8;
                int gn = bn + wn * 16 + nt * 8 + tig * 2 + (r & 1);
                float v = acc[mt][nt][r];
                if (bias) v += bias[gn];
                if (act == 1) v = v / (1.f + __expf(-v));
                else if (act == 2) v = 1.f / (1.f + __expf(-v));
                else if (act == 3) v = (gn <= gm) ? v * 0.125f : -1e30f;
                if (mulp) v *= mulp[(long)gm * ldc + gn];
                if (resp) v += resp[(long)gm * ldc + gn];
                C[(long)gm * ldc + gn] = v;
            }
}

// ---------------- SIMT GEMM fallback (small N; float inputs) ----------------
__global__ void gemm_k(const float* __restrict__ A, const float* __restrict__ Bm,
                       const float* __restrict__ bias, const float* __restrict__ mulb,
                       const float* __restrict__ resb, float* __restrict__ C,
                       int M, int N, int K, int lda, int ldb, int ldc,
                       long sA, long sB, long sC, int act) {
    int bz = blockIdx.z;
    A += (long)bz * sA;
    Bm += (long)bz * sB;
    C += (long)bz * sC;
    const float* mulp = mulb ? mulb + (long)bz * sC : nullptr;
    const float* resp = resb ? resb + (long)bz * sC : nullptr;

    int bm = blockIdx.y * 64, bn = blockIdx.x * 64;
    __shared__ float As[16][68];
    __shared__ float Bs[16][68];
    int tid = threadIdx.x;
    int ty = tid >> 4, tx = tid & 15;
    int aRow = tid >> 2;
    int aColBase = (tid & 3) * 4;
    int bRow = tid >> 4;
    int bColBase = (tid & 15) * 4;

    float acc[4][4];
#pragma unroll
    for (int i = 0; i < 4; i++)
#pragma unroll
        for (int j = 0; j < 4; j++) acc[i][j] = 0.f;

    for (int k0 = 0; k0 < K; k0 += 16) {
#pragma unroll
        for (int i = 0; i < 4; i++) {
            int kk = aColBase + i;
            int gm = bm + aRow, gk = k0 + kk;
            float val = (gm < M) ? A[(long)gm * lda + gk] : 0.f;
            As[kk][aRow] = val;
        }
#pragma unroll
        for (int i = 0; i < 4; i++) {
            int nn = bColBase + i;
            int gn = bn + nn, gk = k0 + bRow;
            float val = (gn < N) ? Bm[(long)gk * ldb + gn] : 0.f;
            Bs[bRow][nn] = val;
        }
        __syncthreads();
#pragma unroll
        for (int kk = 0; kk < 16; kk++) {
            float a[4], b[4];
#pragma unroll
            for (int i = 0; i < 4; i++) a[i] = As[kk][ty * 4 + i];
#pragma unroll
            for (int i = 0; i < 4; i++) b[i] = Bs[kk][tx * 4 + i];
#pragma unroll
            for (int i = 0; i < 4; i++)
#pragma unroll
                for (int j = 0; j < 4; j++) acc[i][j] += a[i] * b[j];
        }
        __syncthreads();
    }

#pragma unroll
    for (int i = 0; i < 4; i++) {
        int gm = bm + ty * 4 + i;
        if (gm >= M) continue;
#pragma unroll
        for (int j = 0; j < 4; j++) {
            int gn = bn + tx * 4 + j;
            if (gn >= N) continue;
            float v = acc[i][j];
            if (bias) v += bias[gn];
            if (act == 1) v = v / (1.f + __expf(-v));
            else if (act == 2) v = 1.f / (1.f + __expf(-v));
            if (mulp) v *= mulp[(long)gm * ldc + gn];
            if (resp) v += resp[(long)gm * ldc + gn];
            C[(long)gm * ldc + gn] = v;
        }
    }
}

// ---------------- group norm over 64 (l2norm or rmsnorm*w) ----------------
__global__ void groupnorm64_k(float* __restrict__ x, const float* __restrict__ w, int mode) {
    int g = blockIdx.x * 8 + (threadIdx.x >> 5);  // group over T*H
    int lane = threadIdx.x & 31;
    float* p = x + (size_t)g * 64;
    float a = p[lane], b = p[lane + 32];
    float s = a * a + b * b;
#pragma unroll
    for (int off = 16; off; off >>= 1) s += __shfl_xor_sync(0xffffffffu, s, off);
    float r = (mode == 0) ? rsqrtf(s + 1e-6f) : rsqrtf(s * (1.f / 64.f) + 1e-6f);
    float wa = mode ? w[lane] : 1.f;
    float wb = mode ? w[lane + 32] : 1.f;
    p[lane] = a * r * wa;
    p[lane + 32] = b * r * wb;
}

// ---------------- row rmsnorm over D ----------------
__global__ void rmsnorm_row_k(const float* __restrict__ x, const float* __restrict__ w,
                              float* __restrict__ out) {
    int t = blockIdx.x;
    const float* p = x + (size_t)t * D;
    __shared__ float red[256];
    float s = 0.f;
    for (int i = threadIdx.x; i < D; i += 256) {
        float v = p[i];
        s += v * v;
    }
    red[threadIdx.x] = s;
    __syncthreads();
    for (int off = 128; off; off >>= 1) {
        if (threadIdx.x < off) red[threadIdx.x] += red[threadIdx.x + off];
        __syncthreads();
    }
    float r = rsqrtf(red[0] * (1.f / D) + 1e-6f);
    for (int i = threadIdx.x; i < D; i += 256)
        out[(size_t)t * D + i] = p[i] * r * w[i];
}

// ---------------- DeltaNet sequential scan (R3 original) ----------------
__global__ void deltanet_scan_k(const float* __restrict__ q, const float* __restrict__ k,
                                const float* __restrict__ v, const float* __restrict__ beta,
                                float* __restrict__ o) {
    int h = blockIdx.x;
    int tid = threadIdx.x;
    int j = tid >> 2;
    int r = tid & 3;
    __shared__ float sk[2][64], sq[2][64], sv[2][64], sb[2];

    float s[16];
#pragma unroll
    for (int i = 0; i < 16; i++) s[i] = 0.f;

    if (tid < 64) sk[0][tid] = k[(size_t)h * 64 + tid];
    else if (tid < 128) sq[0][tid - 64] = q[(size_t)h * 64 + (tid - 64)];
    else if (tid < 192) sv[0][tid - 128] = v[(size_t)h * 64 + (tid - 128)];
    else if (tid == 192) sb[0] = beta[h];
    __syncthreads();

    for (int t = 0; t < T; t++) {
        int cur = t & 1, nxt = cur ^ 1;
        float pre = 0.f;
        bool havePre = (t + 1 < T) && (tid <= 192);
        if (havePre) {
            int tt = t + 1;
            if (tid < 64) pre = k[(size_t)tt * D + h * 64 + tid];
            else if (tid < 128) pre = q[(size_t)tt * D + h * 64 + (tid - 64)];
            else if (tid < 192) pre = v[(size_t)tt * D + h * 64 + (tid - 128)];
            else pre = beta[tt * H + h];
        }

        float p0 = 0.f, p1 = 0.f;
#pragma unroll
        for (int i = 0; i < 16; i += 2) {
            p0 += sk[cur][r * 16 + i] * s[i];
            p1 += sk[cur][r * 16 + i + 1] * s[i + 1];
        }
        float p = p0 + p1;
        p += __shfl_xor_sync(0xffffffffu, p, 1);
        p += __shfl_xor_sync(0xffffffffu, p, 2);

        float delta = sb[cur] * (sv[cur][j] - p);

        float o0 = 0.f, o1 = 0.f;
#pragma unroll
        for (int i = 0; i < 16; i += 2) {
            s[i] += sk[cur][r * 16 + i] * delta;
            o0 += sq[cur][r * 16 + i] * s[i];
            s[i + 1] += sk[cur][r * 16 + i + 1] * delta;
            o1 += sq[cur][r * 16 + i + 1] * s[i + 1];
        }
        float oo = o0 + o1;
        oo += __shfl_xor_sync(0xffffffffu, oo, 1);
        oo += __shfl_xor_sync(0xffffffffu, oo, 2);
        if (r == 0) o[(size_t)t * D + h * 64 + j] = oo;

        if (havePre) {
            if (tid < 64) sk[nxt][tid] = pre;
            else if (tid < 128) sq[nxt][tid - 64] = pre;
            else if (tid < 192) sv[nxt][tid - 128] = pre;
            else sb[nxt] = pre;
        }
        __syncthreads();
    }
}

// ---------------- row softmax over 1024 ----------------
__global__ void softmax_k(float* __restrict__ scores) {
    size_t row = blockIdx.x;  // h*T + t
    float* p = scores + row * T;
    __shared__ float red[256];
    int tid = threadIdx.x;

    float v4[4];
    float m = -1e30f;
#pragma unroll
    for (int i = 0; i < 4; i++) {
        v4[i] = p[tid + i * 256];
        m = fmaxf(m, v4[i]);
    }
    red[tid] = m;
    __syncthreads();
    for (int off = 128; off; off >>= 1) {
        if (tid < off) red[tid] = fmaxf(red[tid], red[tid + off]);
        __syncthreads();
    }
    m = red[0];
    __syncthreads();

    float s = 0.f;
#pragma unroll
    for (int i = 0; i < 4; i++) {
        v4[i] = __expf(v4[i] - m);
        s += v4[i];
    }
    red[tid] = s;
    __syncthreads();
    for (int off = 128; off; off >>= 1) {
        if (tid < off) red[tid] += red[tid + off];
        __syncthreads();
    }
    float inv = 1.f / red[0];
#pragma unroll
    for (int i = 0; i < 4; i++) p[tid + i * 256] = v4[i] * inv;
}

// ---------------- host orchestration ----------------
static uint2 *s_asp, *s_bsp, *s_ktp, *s_vcp;

static void presplitA(const float* src, int nElts) {
    presplitA_k<<<(nElts / 2 + 255) / 256, 256>>>(src, s_asp, nElts / 2);
}
static void presplitB(const float* src, int K, int N) {
    presplitB_k<<<((K / 2) * N + 255) / 256, 256>>>(src, s_bsp, K, N);
}
// tcgemm on pre-split operands (A = s_asp, B = s_bsp). K in floats.
static void tc_gemm(const float* bias, const float* mulb, const float* resb, float* C,
                    int M, int N, int K, int ldb, int ldc, int act,
                    int batch = 1, long sApairs = 0, long sBpairs = 0, long sC = 0,
                    int ldapairs = -1) {
    if (ldapairs < 0) ldapairs = K / 2;
    dim3 g(N / 64, M / 64, batch);
    tcgemm_k<<<g, 256>>>(s_asp, s_bsp, bias, mulb, resb, C, M, N, K / 2, ldapairs, ldb, ldc,
                         sApairs, sBpairs, sC, act);
}

extern "C" void kernel_launch(void* const* d_in, const int* in_sizes, int n_in,
                              void* d_out, int out_size) {
    const int* ids = (const int*)d_in[0];
    const float* emb = (const float*)d_in[1];
    const float* enc_Wq = (const float*)d_in[2];
    const float* enc_Wk = (const float*)d_in[3];
    const float* enc_Wv = (const float*)d_in[4];
    const float* enc_Wb = (const float*)d_in[5];
    const float* enc_nw = (const float*)d_in[6];
    const float* enc_Wo = (const float*)d_in[7];
    const float* ck_W = (const float*)d_in[8];
    const float* ck_b = (const float*)d_in[9];
    const float* cv_W = (const float*)d_in[10];
    const float* cv_b = (const float*)d_in[11];
    const float* dn_Wq = (const float*)d_in[12];
    const float* dn_Wk = (const float*)d_in[13];
    const float* dn_Wv = (const float*)d_in[14];
    const float* dn_Wb = (const float*)d_in[15];
    const float* dn_nw = (const float*)d_in[16];
    const float* dn_Wo = (const float*)d_in[17];
    const float* sw_in_w = (const float*)d_in[18];
    const float* sw_post_w = (const float*)d_in[19];
    const float* sw_Wq = (const float*)d_in[20];
    const float* sw_Wo = (const float*)d_in[21];
    const float* sw_up_W = (const float*)d_in[22];
    const float* sw_up_b = (const float*)d_in[23];
    const float* sw_gate_W = (const float*)d_in[24];
    const float* sw_gate_b = (const float*)d_in[25];
    const float* sw_down_W = (const float*)d_in[26];
    const float* sw_down_b = (const float*)d_in[27];
    const float* final_w = (const float*)d_in[28];

    float *hs, *hbuf, *q, *k, *v, *beta, *o, *kc, *vc, *kcr, *scores, *ff1, *ff2, *ct, *st;
    cudaGetSymbolAddress((void**)&hs, g_hs);
    cudaGetSymbolAddress((void**)&hbuf, g_hbuf);
    cudaGetSymbolAddress((void**)&q, g_q);
    cudaGetSymbolAddress((void**)&k, g_k);
    cudaGetSymbolAddress((void**)&v, g_v);
    cudaGetSymbolAddress((void**)&beta, g_beta);
    cudaGetSymbolAddress((void**)&o, g_o);
    cudaGetSymbolAddress((void**)&kc, g_kc);
    cudaGetSymbolAddress((void**)&vc, g_vc);
    cudaGetSymbolAddress((void**)&kcr, g_kcr);
    cudaGetSymbolAddress((void**)&scores, g_scores);
    cudaGetSymbolAddress((void**)&ff1, g_ff1);
    cudaGetSymbolAddress((void**)&ff2, g_ff2);
    cudaGetSymbolAddress((void**)&ct, g_cos);
    cudaGetSymbolAddress((void**)&st, g_sin);
    cudaGetSymbolAddress((void**)&s_asp, g_asp);
    cudaGetSymbolAddress((void**)&s_bsp, g_bsp);
    cudaGetSymbolAddress((void**)&s_ktp, g_ktp);
    cudaGetSymbolAddress((void**)&s_vcp, g_vcp);

    embed_k<<<T, 256>>>(ids, emb, hs);
    rope_tab_k<<<T, 32>>>(ct, st);

    auto deltanet = [&](const float* Wq, const float* Wk, const float* Wv, const float* Wb,
                        const float* nw, const float* Wo) {
        presplitA(hs, T * D);  // hs split once for q/k/v
        presplitB(Wq, D, D);
        tc_gemm(nullptr, nullptr, nullptr, q, T, D, D, D, D, 1);
        presplitB(Wk, D, D);
        tc_gemm(nullptr, nullptr, nullptr, k, T, D, D, D, D, 1);
        presplitB(Wv, D, D);
        tc_gemm(nullptr, nullptr, nullptr, v, T, D, D, D, D, 1);
        {
            dim3 g((H + 63) / 64, T / 64, 1);
            gemm_k<<<g, 256>>>(hs, Wb, nullptr, nullptr, nullptr, beta, T, H, D, D, H, H,
                               0, 0, 0, 2);
        }
        groupnorm64_k<<<T * H / 8, 256>>>(q, nullptr, 0);
        groupnorm64_k<<<T * H / 8, 256>>>(k, nullptr, 0);
        deltanet_scan_k<<<H, 256>>>(q, k, v, beta, o);
        groupnorm64_k<<<T * H / 8, 256>>>(o, nw, 1);
        presplitA(o, T * D);
        presplitB(Wo, D, D);
        tc_gemm(nullptr, nullptr, nullptr, hs, T, D, D, D, D, 0);
    };

    for (int l = 0; l < 4; l++)
        deltanet(enc_Wq + (long)l * D * D, enc_Wk + (long)l * D * D, enc_Wv + (long)l * D * D,
                 enc_Wb + (long)l * D * H, enc_nw + (long)l * DHD, enc_Wo + (long)l * D * D);

    presplitA(hs, T * D);
    presplitB(ck_W, D, D);
    tc_gemm(ck_b, nullptr, nullptr, kc, T, D, D, D, D, 0);
    presplitB(cv_W, D, D);
    tc_gemm(cv_b, nullptr, nullptr, vc, T, D, D, D, D, 0);
    rope_apply_k<<<(T * H * 32 + 255) / 256, 256>>>(kc, kcr, ct, st);

    // shared-by-both-switchers pre-splits (kcr^T per head, vc)
    presplitKT_k<<<dim3(T / 32, H), 256>>>(kcr, s_ktp);
    presplitB_k<<<((T / 2) * D + 255) / 256, 256>>>(vc, s_vcp, T, D);

    auto switcher = [&](int j) {
        rmsnorm_row_k<<<T, 256>>>(hs, sw_in_w + (long)j * D, hbuf);
        presplitA(hbuf, T * D);
        presplitB(sw_Wq + (long)j * D * D, D, D);
        tc_gemm(nullptr, nullptr, nullptr, q, T, D, D, D, D, 0);
        rope_apply_k<<<(T * H * 32 + 255) / 256, 256>>>(q, q, ct, st);
        // scores = tril(q @ k^T) / 8 on tensor cores, batched over heads
        presplitA(q, T * D);
        tcgemm_k<<<dim3(T / 64, T / 64, H), 256>>>(
            s_asp, s_ktp, nullptr, nullptr, nullptr, scores,
            T, T, 32, D / 2, H * T, T, /*sAp=*/32, /*sBp=*/T, (long)T * T, 3);
        softmax_k<<<H * T, 256>>>(scores);
        // att @ V, batched over heads: A = scores pairs, B = vc pairs (cached)
        presplitA(scores, H * T * T);
        tcgemm_k<<<dim3(1, T / 64, H), 256>>>(
            s_asp, s_vcp, nullptr, nullptr, nullptr, o,
            T, DHD, T / 2, T / 2, D, D, (long)T * T / 2, 64, 64, 0);
        presplitA(o, T * D);
        presplitB(sw_Wo + (long)j * D * D, D, D);
        tc_gemm(nullptr, nullptr, hs, hs, T, D, D, D, D, 0);
        rmsnorm_row_k<<<T, 256>>>(hs, sw_post_w + (long)j * D, hbuf);
        presplitA(hbuf, T * D);
        presplitB(sw_up_W + (long)j * D * DFF, D, DFF);
        tc_gemm(sw_up_b + (long)j * DFF, nullptr, nullptr, ff1, T, DFF, D, DFF, DFF, 0);
        presplitB(sw_gate_W + (long)j * D * DFF, D, DFF);
        tc_gemm(sw_gate_b + (long)j * DFF, ff1, nullptr, ff2, T, DFF, D, DFF, DFF, 2);
        presplitA(ff2, T * DFF);
        presplitB(sw_down_W + (long)j * DFF * D, DFF, D);
        tc_gemm(sw_down_b + (long)j * D, nullptr, hs, hs, T, D, DFF, D, D, 0);
    };

    switcher(0);
    deltanet(dn_Wq, dn_Wk, dn_Wv, dn_Wb, dn_nw, dn_Wo);
    switcher(1);
    deltanet(dn_Wq + (long)D * D, dn_Wk + (long)D * D, dn_Wv + (long)D * D,
             dn_Wb + (long)D * H, dn_nw + DHD, dn_Wo + (long)D * D);

    rmsnorm_row_k<<<T, 256>>>(hs, final_w, (float*)d_out);
}